// round 1
// baseline (speedup 1.0000x reference)
#include <cuda_runtime.h>
#include <math.h>

// ---------------- problem constants ----------------
#define BATCH 8
#define CIN   64
#define COUT  64
#define KS    3
#define SDIM  512
#define HH    256
#define WW    256
#define TAPS  9

#define CONV_SCALE (1.0f / 24.0f)               // 1/sqrt(64*9)
#define MOD_SCALE  (0.04419417382415922f)       // 1/sqrt(512)
#define EPSV       (1e-8f)

// ---------------- device scratch (no allocations allowed) ----------------
__device__ float g_s[BATCH * CIN];                       // modulation scalars
__device__ float g_w[BATCH * COUT * CIN * TAPS];         // demodulated weights (1.18 MB)

// ---------------- kernel A: s[b][ci] = mod_scale * <style_b, mw_ci> + bias_ci ----
__global__ void style_mod_kernel(const float* __restrict__ style,
                                 const float* __restrict__ mw,
                                 const float* __restrict__ mb) {
    int ci = blockIdx.x;        // 0..63
    int b  = blockIdx.y;        // 0..7
    int tid = threadIdx.x;      // 128 threads

    const float* sp = style + b * SDIM;
    const float* wp = mw + ci * SDIM;
    float sum = 0.f;
    for (int k = tid; k < SDIM; k += 128)
        sum += sp[k] * wp[k];

    // warp reduce
    #pragma unroll
    for (int off = 16; off > 0; off >>= 1)
        sum += __shfl_xor_sync(0xFFFFFFFFu, sum, off);

    __shared__ float red[4];
    if ((tid & 31) == 0) red[tid >> 5] = sum;
    __syncthreads();
    if (tid == 0) {
        float t = red[0] + red[1] + red[2] + red[3];
        g_s[b * CIN + ci] = t * MOD_SCALE + mb[ci];
    }
}

// ---------------- kernel B: demodulated per-sample weights ----------------
// block = (co, b), 576 threads, one per (ci, tap)
__global__ void demod_kernel(const float* __restrict__ w) {
    int co = blockIdx.x;
    int b  = blockIdx.y;
    int tid = threadIdx.x;      // 0..575
    int ci  = tid / TAPS;
    int tap = tid - ci * TAPS;

    float val = CONV_SCALE * w[(co * CIN + ci) * TAPS + tap] * g_s[b * CIN + ci];

    __shared__ float red[576];
    red[tid] = val * val;
    __syncthreads();
    if (tid < 64) red[tid] += red[tid + 512];
    __syncthreads();
    for (int s = 256; s > 0; s >>= 1) {
        if (tid < s) red[tid] += red[tid + s];
        __syncthreads();
    }
    float demod = rsqrtf(red[0] + EPSV);
    g_w[((b * COUT + co) * CIN + ci) * TAPS + tap] = val * demod;
}

// ---------------- kernel C: direct 3x3 conv ----------------
// grid: (8 xtiles, 8 ytiles, B * 8 cogroups), block 256 threads
// block computes 32x32 pixels x 8 output channels for one batch sample.
// CIN processed in chunks of 8 via shared memory.
#define CI_C 8
#define TILE 32
#define SROW 35    // padded row stride (34 used), odd stride breaks 2-stride bank pattern

__global__ __launch_bounds__(256, 3)
void conv_kernel(const float* __restrict__ in, float* __restrict__ out) {
    __shared__ float sIn[CI_C][TILE + 2][SROW];
    __shared__ float sW[8][CI_C][TAPS];

    const int tid = threadIdx.x;
    const int tx = tid & 15;        // 0..15
    const int ty = tid >> 4;        // 0..15
    const int x0 = blockIdx.x * TILE;
    const int y0 = blockIdx.y * TILE;
    const int b   = blockIdx.z >> 3;
    const int co0 = (blockIdx.z & 7) * 8;

    float acc[8][4];
    #pragma unroll
    for (int co = 0; co < 8; co++)
        #pragma unroll
        for (int p = 0; p < 4; p++)
            acc[co][p] = 0.f;

    const float* inb = in + (size_t)b * CIN * HH * WW;

    for (int ci0 = 0; ci0 < CIN; ci0 += CI_C) {
        // ---- load input tile (with halo, zero padded) ----
        for (int idx = tid; idx < CI_C * 34 * 34; idx += 256) {
            int ci  = idx / (34 * 34);
            int rem = idx - ci * 34 * 34;
            int iy  = rem / 34;
            int ix  = rem - iy * 34;
            int gy = y0 + iy - 1;
            int gx = x0 + ix - 1;
            float v = 0.f;
            if ((unsigned)gy < HH && (unsigned)gx < WW)
                v = inb[((size_t)(ci0 + ci) * HH + gy) * WW + gx];
            sIn[ci][iy][ix] = v;
        }
        // ---- load weight chunk ----
        for (int idx = tid; idx < 8 * CI_C * TAPS; idx += 256) {
            int col = idx / (CI_C * TAPS);
            int rem = idx - col * (CI_C * TAPS);
            int ci  = rem / TAPS;
            int tap = rem - ci * TAPS;
            sW[col][ci][tap] =
                g_w[((b * COUT + (co0 + col)) * CIN + (ci0 + ci)) * TAPS + tap];
        }
        __syncthreads();

        // ---- compute ----
        #pragma unroll
        for (int ci = 0; ci < CI_C; ci++) {
            float p[4][4];
            #pragma unroll
            for (int r = 0; r < 4; r++)
                #pragma unroll
                for (int c = 0; c < 4; c++)
                    p[r][c] = sIn[ci][2 * ty + r][2 * tx + c];

            #pragma unroll
            for (int co = 0; co < 8; co++) {
                float w0 = sW[co][ci][0], w1 = sW[co][ci][1], w2 = sW[co][ci][2];
                float w3 = sW[co][ci][3], w4 = sW[co][ci][4], w5 = sW[co][ci][5];
                float w6 = sW[co][ci][6], w7 = sW[co][ci][7], w8 = sW[co][ci][8];
                #pragma unroll
                for (int ry = 0; ry < 2; ry++) {
                    #pragma unroll
                    for (int rx = 0; rx < 2; rx++) {
                        float a = acc[co][ry * 2 + rx];
                        a = fmaf(w0, p[ry + 0][rx + 0], a);
                        a = fmaf(w1, p[ry + 0][rx + 1], a);
                        a = fmaf(w2, p[ry + 0][rx + 2], a);
                        a = fmaf(w3, p[ry + 1][rx + 0], a);
                        a = fmaf(w4, p[ry + 1][rx + 1], a);
                        a = fmaf(w5, p[ry + 1][rx + 2], a);
                        a = fmaf(w6, p[ry + 2][rx + 0], a);
                        a = fmaf(w7, p[ry + 2][rx + 1], a);
                        a = fmaf(w8, p[ry + 2][rx + 2], a);
                        acc[co][ry * 2 + rx] = a;
                    }
                }
            }
        }
        __syncthreads();
    }

    // ---- write out ----
    const int px = x0 + 2 * tx;
    const int py = y0 + 2 * ty;
    #pragma unroll
    for (int co = 0; co < 8; co++) {
        float* op = out + (((size_t)b * COUT + (co0 + co)) * HH + py) * WW + px;
        op[0]      = acc[co][0];
        op[1]      = acc[co][1];
        op[WW]     = acc[co][2];
        op[WW + 1] = acc[co][3];
    }
}

// ---------------- launch ----------------
extern "C" void kernel_launch(void* const* d_in, const int* in_sizes, int n_in,
                              void* d_out, int out_size) {
    const float* input      = (const float*)d_in[0];  // (8,64,256,256)
    const float* style      = (const float*)d_in[1];  // (8,512)
    const float* weight     = (const float*)d_in[2];  // (1,64,64,3,3)
    const float* mod_weight = (const float*)d_in[3];  // (64,512)
    const float* mod_bias   = (const float*)d_in[4];  // (64,)
    float* out = (float*)d_out;                       // (8,64,256,256)

    style_mod_kernel<<<dim3(CIN, BATCH), 128>>>(style, mod_weight, mod_bias);
    demod_kernel<<<dim3(COUT, BATCH), 576>>>(weight);
    conv_kernel<<<dim3(WW / TILE, HH / TILE, BATCH * 8), 256>>>(input, out);
}

// round 3
// speedup vs baseline: 1.7149x; 1.7149x over previous
#include <cuda_runtime.h>
#include <cuda_bf16.h>
#include <cstdint>
#include <math.h>

// ---------------- problem constants ----------------
#define BATCH 8
#define CIN   64
#define COUT  64
#define SDIM  512
#define HH    256
#define WW    256
#define TAPS  9

#define CONV_SCALE (1.0f / 24.0f)               // 1/sqrt(64*9)
#define MOD_SCALE  (0.04419417382415922f)       // 1/sqrt(512)
#define EPSV       (1e-8f)

#define PROWS 258   // 256 image rows + 1 zero pad row top & bottom

// ---------------- device scratch ----------------
__device__ float g_s[BATCH * CIN];
// transposed padded input, bf16 hi/lo planes: [b][row 0..257][x 0..255][ci 0..63]
__device__ __nv_bfloat16 g_in_h[(size_t)BATCH * PROWS * WW * CIN];
__device__ __nv_bfloat16 g_in_l[(size_t)BATCH * PROWS * WW * CIN];
// demodulated weights bf16 hi/lo: [b][tap][plane][co][ci]
__device__ __nv_bfloat16 g_wt[BATCH * TAPS * 2 * COUT * CIN];

// ---------------- helpers ----------------
__device__ __forceinline__ uint32_t smem_u32(const void* p) {
    uint32_t a;
    asm("{ .reg .u64 t; cvta.to.shared.u64 t, %1; cvt.u32.u64 %0, t; }" : "=r"(a) : "l"(p));
    return a;
}
__device__ __forceinline__ void ldsm4(uint32_t (&r)[4], uint32_t addr) {
    asm volatile("ldmatrix.sync.aligned.m8n8.x4.shared.b16 {%0,%1,%2,%3}, [%4];"
                 : "=r"(r[0]), "=r"(r[1]), "=r"(r[2]), "=r"(r[3]) : "r"(addr));
}
__device__ __forceinline__ void mma16816(float (&c)[4], const uint32_t (&a)[4],
                                         const uint32_t b0, const uint32_t b1) {
    asm volatile(
        "mma.sync.aligned.m16n8k16.row.col.f32.bf16.bf16.f32 "
        "{%0,%1,%2,%3}, {%4,%5,%6,%7}, {%8,%9}, {%0,%1,%2,%3};"
        : "+f"(c[0]), "+f"(c[1]), "+f"(c[2]), "+f"(c[3])
        : "r"(a[0]), "r"(a[1]), "r"(a[2]), "r"(a[3]), "r"(b0), "r"(b1));
}
__device__ __forceinline__ void cpasync16(uint32_t dst, const void* src) {
    asm volatile("cp.async.cg.shared.global [%0], [%1], 16;" :: "r"(dst), "l"(src) : "memory");
}
__device__ __forceinline__ void cpcommit() { asm volatile("cp.async.commit_group;" ::: "memory"); }
__device__ __forceinline__ void cpwait0()  { asm volatile("cp.async.wait_group 0;" ::: "memory"); }

__device__ __forceinline__ uint32_t swA(uint32_t o) { return o ^ ((o >> 3) & 0x70u); }
__device__ __forceinline__ uint32_t swW(uint32_t o) { return o ^ (((o >> 7) & 1u) << 4); }

// ---------------- kernel A: style modulation scalars ----------------
__global__ void style_mod_kernel(const float* __restrict__ style,
                                 const float* __restrict__ mw,
                                 const float* __restrict__ mb) {
    int ci = blockIdx.x;
    int b  = blockIdx.y;
    int tid = threadIdx.x;
    const float* sp = style + b * SDIM;
    const float* wp = mw + ci * SDIM;
    float sum = 0.f;
    for (int k = tid; k < SDIM; k += 128) sum += sp[k] * wp[k];
    #pragma unroll
    for (int off = 16; off > 0; off >>= 1)
        sum += __shfl_xor_sync(0xFFFFFFFFu, sum, off);
    __shared__ float red[4];
    if ((tid & 31) == 0) red[tid >> 5] = sum;
    __syncthreads();
    if (tid == 0)
        g_s[b * CIN + ci] = (red[0] + red[1] + red[2] + red[3]) * MOD_SCALE + mb[ci];
}

// ---------------- kernel B: demodulated weights -> bf16 hi/lo --------------
__global__ void demod_kernel(const float* __restrict__ w) {
    int co = blockIdx.x;
    int b  = blockIdx.y;
    int tid = threadIdx.x;      // 0..575 = (ci, tap)
    int ci  = tid / TAPS;
    int tap = tid - ci * TAPS;

    float val = CONV_SCALE * w[(co * CIN + ci) * TAPS + tap] * g_s[b * CIN + ci];

    __shared__ float red[576];
    red[tid] = val * val;
    __syncthreads();
    if (tid < 64) red[tid] += red[tid + 512];
    __syncthreads();
    for (int s = 256; s > 0; s >>= 1) {
        if (tid < s) red[tid] += red[tid + s];
        __syncthreads();
    }
    float vd = val * rsqrtf(red[0] + EPSV);

    __nv_bfloat16 h = __float2bfloat16_rn(vd);
    float lo = vd - __bfloat162float(h);
    __nv_bfloat16 l = __float2bfloat16_rn(lo);
    size_t base = ((((size_t)b * TAPS + tap) * 2 + 0) * COUT + co) * CIN + ci;
    g_wt[base] = h;
    g_wt[base + (size_t)COUT * CIN] = l;
}

// ---------------- kernel C: convert + transpose input to bf16 hi/lo --------
__global__ void convert_kernel(const float* __restrict__ in) {
    __shared__ float s[64][33];
    const int tid = threadIdx.x;
    const int x0 = blockIdx.x * 32;
    const int y  = blockIdx.y;
    const int b  = blockIdx.z;

    for (int i = tid; i < 2048; i += 256) {
        int ci = i >> 5, x = i & 31;
        s[ci][x] = in[(((size_t)b * CIN + ci) * HH + y) * WW + x0 + x];
    }
    __syncthreads();

    const int x   = tid >> 3;
    const int ci0 = (tid & 7) << 3;
    float v[8];
    #pragma unroll
    for (int k = 0; k < 8; k++) v[k] = s[ci0 + k][x];

    uint32_t uh[4], ul[4];
    #pragma unroll
    for (int k = 0; k < 4; k++) {
        __nv_bfloat16 h0 = __float2bfloat16_rn(v[2 * k]);
        __nv_bfloat16 h1 = __float2bfloat16_rn(v[2 * k + 1]);
        float l0 = v[2 * k]     - __bfloat162float(h0);
        float l1 = v[2 * k + 1] - __bfloat162float(h1);
        __nv_bfloat162 hp = __halves2bfloat162(h0, h1);
        __nv_bfloat162 lp = __halves2bfloat162(__float2bfloat16_rn(l0),
                                               __float2bfloat16_rn(l1));
        uh[k] = *reinterpret_cast<uint32_t*>(&hp);
        ul[k] = *reinterpret_cast<uint32_t*>(&lp);
    }
    size_t e = ((((size_t)b * PROWS + y + 1) * WW + x0 + x) * CIN + ci0) >> 3;
    ((uint4*)g_in_h)[e] = make_uint4(uh[0], uh[1], uh[2], uh[3]);
    ((uint4*)g_in_l)[e] = make_uint4(ul[0], ul[1], ul[2], ul[3]);
}

__global__ void pad_kernel() {
    int idx = blockIdx.x * 256 + threadIdx.x;      // 32768 uint4 per plane
    if (idx >= 32768) return;
    int b   = idx >> 12;
    int r   = (idx >> 11) & 1;
    int rem = idx & 2047;
    size_t row = (size_t)b * PROWS + (r ? (PROWS - 1) : 0);
    size_t u = row * (WW * CIN / 8) + rem;
    ((uint4*)g_in_h)[u] = make_uint4(0, 0, 0, 0);
    ((uint4*)g_in_l)[u] = make_uint4(0, 0, 0, 0);
}

// ---------------- kernel D: mma.sync implicit conv ----------------
// CTA = (xhalf, y, b): 128 px x 64 co.  8 warps: 4 in M (32px) x 2 in N (32co).
// SMEM: A [plane2][row3][px130][ci64] bf16 (swA), W ping-pong k16 chunks (swW).
#define A_PLANE  49920u            // 390 * 128
#define A_BYTES  99840u
#define W_BUF    36864u
#define SMEM_TOTAL (A_BYTES + 2 * W_BUF)   // 173568

__global__ __launch_bounds__(256, 1)
void conv_kernel(float* __restrict__ out) {
    extern __shared__ char smem[];
    const uint32_t sb = smem_u32(smem);
    const int tid  = threadIdx.x;
    const int wid  = tid >> 5;
    const int lane = tid & 31;
    const int xh = blockIdx.x;
    const int y  = blockIdx.y;
    const int b  = blockIdx.z;

    const int mwarp = wid & 3;
    const int nwarp = wid >> 2;
    const uint32_t px0 = mwarp * 32;
    const uint32_t co0 = nwarp * 32;

    // ldmatrix per-thread components
    const uint32_t arow = lane & 15;
    const uint32_t khA  = ((lane >> 4) & 1) * 16;
    const uint32_t brow = (lane & 7) | ((lane >> 1) & 8);
    const uint32_t khB  = ((lane >> 3) & 1) * 16;

    // ---- prefetch W chunk 0 ----
    {
        for (int j = tid; j < 2304; j += 256) {
            int h = j & 1, n = (j >> 1) & 63, tp = j >> 7;
            const uint4* src = ((const uint4*)g_wt) +
                ((size_t)(b * 18 + tp) * 64 + n) * 8 + 0 * 2 + h;
            uint32_t o = (uint32_t)(tp * 64 + n) * 32 + h * 16;
            cpasync16(sb + A_BYTES + swW(o), src);
        }
        cpcommit();
    }

    // ---- stage A: 2 planes x 3 rows x 130 px x 128B ----
    {
        const uint4* srcH = (const uint4*)g_in_h;
        const uint4* srcL = (const uint4*)g_in_l;
        for (int idx = tid; idx < 6240; idx += 256) {
            int plane = idx / 3120;
            int rem   = idx - plane * 3120;
            int rr    = rem >> 3;           // r*130 + i
            int g     = rem & 7;
            int r     = rr / 130;
            int i     = rr - r * 130;
            int gx    = xh * 128 + i - 1;
            uint4 v = make_uint4(0, 0, 0, 0);
            if ((unsigned)gx < 256u) {
                size_t s = ((size_t)(b * PROWS + y + r) * 256 + gx) * 8 + g;
                v = plane ? srcL[s] : srcH[s];
            }
            uint32_t off = (uint32_t)(plane * 390 + rr) * 128u + (uint32_t)g * 16u;
            *(uint4*)(smem + swA(off)) = v;
        }
    }
    cpwait0();
    __syncthreads();

    float acc[2][4][4];
    #pragma unroll
    for (int mf = 0; mf < 2; mf++)
        #pragma unroll
        for (int nf = 0; nf < 4; nf++)
            #pragma unroll
            for (int c = 0; c < 4; c++) acc[mf][nf][c] = 0.f;

    // ---- main loop over k16 chunks ----
    for (int kc = 0; kc < 4; kc++) {
        // prefetch next W chunk into other buffer
        if (kc < 3) {
            uint32_t dstb = sb + A_BYTES + ((kc + 1) & 1) * W_BUF;
            for (int j = tid; j < 2304; j += 256) {
                int h = j & 1, n = (j >> 1) & 63, tp = j >> 7;
                const uint4* src = ((const uint4*)g_wt) +
                    ((size_t)(b * 18 + tp) * 64 + n) * 8 + (kc + 1) * 2 + h;
                uint32_t o = (uint32_t)(tp * 64 + n) * 32 + h * 16;
                cpasync16(dstb + swW(o), src);
            }
            cpcommit();
        }

        const uint32_t kb = kc * 32;
        const uint32_t wcur = sb + A_BYTES + (kc & 1) * W_BUF;

        #pragma unroll
        for (int dy = 0; dy < 3; dy++) {
            #pragma unroll
            for (int dx = 0; dx < 3; dx++) {
                const uint32_t tp = (uint32_t)(dy * 3 + dx) * 2;

                uint32_t ah[2][4], al[2][4];
                #pragma unroll
                for (int mf = 0; mf < 2; mf++) {
                    uint32_t i  = px0 + mf * 16 + arow + dx;
                    uint32_t o0 = ((uint32_t)(dy * 130) + i) * 128u + kb + khA;
                    uint32_t o1 = o0 + A_PLANE;
                    ldsm4(ah[mf], sb + swA(o0));
                    ldsm4(al[mf], sb + swA(o1));
                }

                uint32_t bh[4][2], bl[4][2];
                #pragma unroll
                for (int g = 0; g < 2; g++) {
                    uint32_t tmp[4];
                    uint32_t o = (tp * 64u + co0 + g * 16 + brow) * 32u + khB;
                    ldsm4(tmp, wcur + swW(o));
                    bh[g * 2][0] = tmp[0]; bh[g * 2][1] = tmp[1];
                    bh[g * 2 + 1][0] = tmp[2]; bh[g * 2 + 1][1] = tmp[3];
                    uint32_t o2 = o + 2048u;   // plane 1 (tp+1)
                    ldsm4(tmp, wcur + swW(o2));
                    bl[g * 2][0] = tmp[0]; bl[g * 2][1] = tmp[1];
                    bl[g * 2 + 1][0] = tmp[2]; bl[g * 2 + 1][1] = tmp[3];
                }

                // term 0: Ahi * Whi
                #pragma unroll
                for (int mf = 0; mf < 2; mf++)
                    #pragma unroll
                    for (int nf = 0; nf < 4; nf++)
                        mma16816(acc[mf][nf], ah[mf], bh[nf][0], bh[nf][1]);
                // term 1: Alo * Whi
                #pragma unroll
                for (int mf = 0; mf < 2; mf++)
                    #pragma unroll
                    for (int nf = 0; nf < 4; nf++)
                        mma16816(acc[mf][nf], al[mf], bh[nf][0], bh[nf][1]);
                // term 2: Ahi * Wlo
                #pragma unroll
                for (int mf = 0; mf < 2; mf++)
                    #pragma unroll
                    for (int nf = 0; nf < 4; nf++)
                        mma16816(acc[mf][nf], ah[mf], bl[nf][0], bl[nf][1]);
            }
        }

        if (kc < 3) {
            cpwait0();
            __syncthreads();
        }
    }

    // ---- epilogue: transpose through smem, coalesced STG.128 ----
    __syncthreads();   // all ldmatrix reads of A done before overwrite
    float* sOut = (float*)smem;            // [64 co][132 px] floats
    const int g = lane >> 2;
    const int t = lane & 3;
    #pragma unroll
    for (int mf = 0; mf < 2; mf++) {
        #pragma unroll
        for (int nf = 0; nf < 4; nf++) {
            int px = px0 + mf * 16 + g;
            int co = co0 + nf * 8 + 2 * t;
            sOut[co * 132 + px]           = acc[mf][nf][0];
            sOut[(co + 1) * 132 + px]     = acc[mf][nf][1];
            sOut[co * 132 + px + 8]       = acc[mf][nf][2];
            sOut[(co + 1) * 132 + px + 8] = acc[mf][nf][3];
        }
    }
    __syncthreads();

    #pragma unroll
    for (int k = 0; k < 8; k++) {
        int idx = tid + 256 * k;            // 0..2047
        int co = idx >> 5;
        int q  = idx & 31;
        float4 v = *(float4*)&sOut[co * 132 + q * 4];
        *(float4*)(out + (((size_t)b * COUT + co) * HH + y) * WW + xh * 128 + q * 4) = v;
    }
}

// ---------------- launch ----------------
extern "C" void kernel_launch(void* const* d_in, const int* in_sizes, int n_in,
                              void* d_out, int out_size) {
    const float* input      = (const float*)d_in[0];
    const float* style      = (const float*)d_in[1];
    const float* weight     = (const float*)d_in[2];
    const float* mod_weight = (const float*)d_in[3];
    const float* mod_bias   = (const float*)d_in[4];
    float* out = (float*)d_out;

    cudaFuncSetAttribute(conv_kernel,
                         cudaFuncAttributeMaxDynamicSharedMemorySize, SMEM_TOTAL);

    style_mod_kernel<<<dim3(CIN, BATCH), 128>>>(style, mod_weight, mod_bias);
    demod_kernel<<<dim3(COUT, BATCH), 576>>>(weight);
    convert_kernel<<<dim3(8, HH, BATCH), 256>>>(input);
    pad_kernel<<<128, 256>>>();
    conv_kernel<<<dim3(2, HH, BATCH), 256, SMEM_TOTAL>>>(out);
}

// round 4
// speedup vs baseline: 5.4585x; 3.1830x over previous
#include <cuda_runtime.h>
#include <cuda_fp16.h>
#include <cstdint>
#include <math.h>

// ---------------- problem constants ----------------
#define BATCH 8
#define CIN   64
#define COUT  64
#define SDIM  512
#define HH    256
#define WW    256
#define TAPS  9

#define CONV_SCALE (1.0f / 24.0f)
#define MOD_SCALE  (0.04419417382415922f)
#define EPSV       (1e-8f)

#define PROWS 258   // padded rows: 1 zero row top & bottom

// ---------------- device scratch ----------------
__device__ float g_s[BATCH * CIN];
// transposed padded input fp16: [b][prow 0..257][x 0..255][ci 0..63]
__device__ __align__(16) __half g_in[(size_t)BATCH * PROWS * WW * CIN];
// demodulated weights fp16: [b][tap][co][ci]
__device__ __align__(16) __half g_wt[BATCH * TAPS * COUT * CIN];

// ---------------- helpers ----------------
__device__ __forceinline__ uint32_t smem_u32(const void* p) {
    uint32_t a;
    asm("{ .reg .u64 t; cvta.to.shared.u64 t, %1; cvt.u32.u64 %0, t; }" : "=r"(a) : "l"(p));
    return a;
}
__device__ __forceinline__ void ldsm4(uint32_t (&r)[4], uint32_t addr) {
    asm volatile("ldmatrix.sync.aligned.m8n8.x4.shared.b16 {%0,%1,%2,%3}, [%4];"
                 : "=r"(r[0]), "=r"(r[1]), "=r"(r[2]), "=r"(r[3]) : "r"(addr));
}
__device__ __forceinline__ void mma16816(float (&c)[4], const uint32_t (&a)[4],
                                         const uint32_t b0, const uint32_t b1) {
    asm volatile(
        "mma.sync.aligned.m16n8k16.row.col.f32.f16.f16.f32 "
        "{%0,%1,%2,%3}, {%4,%5,%6,%7}, {%8,%9}, {%0,%1,%2,%3};"
        : "+f"(c[0]), "+f"(c[1]), "+f"(c[2]), "+f"(c[3])
        : "r"(a[0]), "r"(a[1]), "r"(a[2]), "r"(a[3]), "r"(b0), "r"(b1));
}
__device__ __forceinline__ void cpasync16(uint32_t dst, const void* src) {
    asm volatile("cp.async.cg.shared.global [%0], [%1], 16;" :: "r"(dst), "l"(src) : "memory");
}
__device__ __forceinline__ void cpcommit() { asm volatile("cp.async.commit_group;" ::: "memory"); }
__device__ __forceinline__ void cpwait0()  { asm volatile("cp.async.wait_group 0;" ::: "memory"); }

__device__ __forceinline__ uint32_t sw128(uint32_t o) { return o ^ ((o >> 3) & 0x70u); }

// ---------------- kernel A: style modulation scalars ----------------
__global__ void style_mod_kernel(const float* __restrict__ style,
                                 const float* __restrict__ mw,
                                 const float* __restrict__ mb) {
    int ci = blockIdx.x;
    int b  = blockIdx.y;
    int tid = threadIdx.x;
    const float* sp = style + b * SDIM;
    const float* wp = mw + ci * SDIM;
    float sum = 0.f;
    for (int k = tid; k < SDIM; k += 128) sum += sp[k] * wp[k];
    #pragma unroll
    for (int off = 16; off > 0; off >>= 1)
        sum += __shfl_xor_sync(0xFFFFFFFFu, sum, off);
    __shared__ float red[4];
    if ((tid & 31) == 0) red[tid >> 5] = sum;
    __syncthreads();
    if (tid == 0)
        g_s[b * CIN + ci] = (red[0] + red[1] + red[2] + red[3]) * MOD_SCALE + mb[ci];
}

// ---------------- kernel B: demodulated weights -> fp16 --------------------
__global__ void demod_kernel(const float* __restrict__ w) {
    int co = blockIdx.x;
    int b  = blockIdx.y;
    int tid = threadIdx.x;      // (ci, tap)
    int ci  = tid / TAPS;
    int tap = tid - ci * TAPS;

    float val = CONV_SCALE * w[(co * CIN + ci) * TAPS + tap] * g_s[b * CIN + ci];

    __shared__ float red[576];
    red[tid] = val * val;
    __syncthreads();
    if (tid < 64) red[tid] += red[tid + 512];
    __syncthreads();
    for (int s = 256; s > 0; s >>= 1) {
        if (tid < s) red[tid] += red[tid + s];
        __syncthreads();
    }
    float vd = val * rsqrtf(red[0] + EPSV);
    g_wt[(((size_t)b * TAPS + tap) * COUT + co) * CIN + ci] = __float2half_rn(vd);
}

// ---------------- kernel C: convert + transpose input to fp16 --------------
__global__ void convert_kernel(const float* __restrict__ in) {
    __shared__ float s[64][33];
    const int tid = threadIdx.x;
    const int x0 = blockIdx.x * 32;
    const int y  = blockIdx.y;
    const int b  = blockIdx.z;

    for (int i = tid; i < 2048; i += 256) {
        int ci = i >> 5, x = i & 31;
        s[ci][x] = in[(((size_t)b * CIN + ci) * HH + y) * WW + x0 + x];
    }
    __syncthreads();

    const int x   = tid >> 3;
    const int ci0 = (tid & 7) << 3;
    uint32_t u[4];
    #pragma unroll
    for (int k = 0; k < 4; k++) {
        __half2 hp = __floats2half2_rn(s[ci0 + 2 * k][x], s[ci0 + 2 * k + 1][x]);
        u[k] = *reinterpret_cast<uint32_t*>(&hp);
    }
    size_t e = ((((size_t)b * PROWS + y + 1) * WW + x0 + x) * CIN + ci0) >> 3;
    ((uint4*)g_in)[e] = make_uint4(u[0], u[1], u[2], u[3]);
}

__global__ void pad_kernel() {
    int idx = blockIdx.x * 256 + threadIdx.x;      // 32768 uint4 total
    if (idx >= 32768) return;
    int b   = idx >> 12;
    int r   = (idx >> 11) & 1;
    int rem = idx & 2047;
    size_t row = (size_t)b * PROWS + (r ? (PROWS - 1) : 0);
    ((uint4*)g_in)[row * 2048 + rem] = make_uint4(0, 0, 0, 0);
}

// ---------------- kernel D: fp16 mma implicit conv, 8-row strips -----------
// CTA = (xh, ychunk, b): 128 px x 64 co x 8 output rows.
// 8 warps: 4 in M (32px) x 2 in N (32co).
// SMEM: W [tap][co][ci] 72KB resident; A = 4-slot row ring (130px x 128B each);
//       OUT staging 64co x 132px f32.
#define W_OFF      0u
#define W_BYTES    73728u
#define RING_OFF   73728u
#define ROW_STRIDE 17408u          // 16640 used, padded to 17*1024
#define OUT_OFF    (RING_OFF + 4u * ROW_STRIDE)          // 143360
#define OUT_BYTES  (64u * 132u * 4u)                     // 33792
#define SMEM_TOTAL (OUT_OFF + OUT_BYTES)                 // 177152

__global__ __launch_bounds__(256, 1)
void conv_kernel(float* __restrict__ out) {
    extern __shared__ char smem[];
    const uint32_t sb = smem_u32(smem);
    const int tid  = threadIdx.x;
    const int wid  = tid >> 5;
    const int lane = tid & 31;
    const int xh = blockIdx.x;
    const int y0 = blockIdx.y * 8;
    const int b  = blockIdx.z;

    const int mwarp = wid & 3;
    const int nwarp = wid >> 2;
    const uint32_t px0 = mwarp * 32;
    const uint32_t co0 = nwarp * 32;

    const uint32_t arow = lane & 15;
    const uint32_t khA  = ((lane >> 4) & 1) * 16;
    const uint32_t brow = (lane & 7) | ((lane >> 1) & 8);
    const uint32_t khB  = ((lane >> 3) & 1) * 16;

    // ---- stage a padded input row into ring slot (cp.async, swizzled) ----
    auto stage_row = [&](int prow) {
        const uint32_t dstb = sb + RING_OFF + ((uint32_t)prow & 3u) * ROW_STRIDE;
        const uint4* src = ((const uint4*)g_in) + ((size_t)(b * PROWS + prow) * 256) * 8;
        #pragma unroll
        for (int k = 0; k < 5; k++) {
            int idx = tid + 256 * k;            // 0..1039 (+pad)
            if (idx < 1040) {
                int px = idx >> 3;              // 0..129
                int g  = idx & 7;
                int gx = xh * 128 + px - 1;
                uint32_t dst = dstb + sw128((uint32_t)px * 128u + (uint32_t)g * 16u);
                if ((unsigned)gx < 256u) {
                    cpasync16(dst, src + (size_t)gx * 8 + g);
                } else {
                    *(uint4*)(smem + (dst - sb)) = make_uint4(0, 0, 0, 0);
                }
            }
        }
    };

    // ---- prologue: stage W + first 3 rows ----
    {
        const uint4* ws = ((const uint4*)g_wt) + (size_t)b * 4608;
        for (int j = tid; j < 4608; j += 256) {
            uint32_t o = (uint32_t)j << 4;      // row*128 + g*16
            cpasync16(sb + W_OFF + sw128(o), ws + j);
        }
    }
    stage_row(y0);
    stage_row(y0 + 1);
    stage_row(y0 + 2);
    cpcommit();
    cpwait0();
    __syncthreads();

    float* sOut = (float*)(smem + OUT_OFF);
    const int eg = lane >> 2;
    const int et = lane & 3;

    for (int yy = 0; yy < 8; yy++) {
        const int y = y0 + yy;
        if (yy < 7) { stage_row(y + 3); cpcommit(); }

        float acc[2][4][4];
        #pragma unroll
        for (int mf = 0; mf < 2; mf++)
            #pragma unroll
            for (int nf = 0; nf < 4; nf++)
                #pragma unroll
                for (int c = 0; c < 4; c++) acc[mf][nf][c] = 0.f;

        for (int kc = 0; kc < 4; kc++) {
            const uint32_t kb = (uint32_t)kc * 32u;
            #pragma unroll
            for (int dy = 0; dy < 3; dy++) {
                const uint32_t slot = sb + RING_OFF + (((uint32_t)(y + dy)) & 3u) * ROW_STRIDE;
                #pragma unroll
                for (int dx = 0; dx < 3; dx++) {
                    const uint32_t tap = (uint32_t)(dy * 3 + dx);

                    uint32_t a[2][4];
                    #pragma unroll
                    for (int mf = 0; mf < 2; mf++) {
                        uint32_t o = (px0 + (uint32_t)mf * 16u + arow + (uint32_t)dx) * 128u
                                     + kb + khA;
                        ldsm4(a[mf], slot + sw128(o));
                    }

                    uint32_t bfr[4][2];
                    #pragma unroll
                    for (int g = 0; g < 2; g++) {
                        uint32_t tmp[4];
                        uint32_t o = (tap * 64u + co0 + (uint32_t)g * 16u + brow) * 128u
                                     + kb + khB;
                        ldsm4(tmp, sb + W_OFF + sw128(o));
                        bfr[g * 2][0]     = tmp[0]; bfr[g * 2][1]     = tmp[1];
                        bfr[g * 2 + 1][0] = tmp[2]; bfr[g * 2 + 1][1] = tmp[3];
                    }

                    #pragma unroll
                    for (int mf = 0; mf < 2; mf++)
                        #pragma unroll
                        for (int nf = 0; nf < 4; nf++)
                            mma16816(acc[mf][nf], a[mf], bfr[nf][0], bfr[nf][1]);
                }
            }
        }

        // ---- epilogue: transpose through smem, coalesced float4 stores ----
        #pragma unroll
        for (int mf = 0; mf < 2; mf++) {
            #pragma unroll
            for (int nf = 0; nf < 4; nf++) {
                int px = px0 + mf * 16 + eg;
                int co = co0 + nf * 8 + 2 * et;
                sOut[co * 132 + px]           = acc[mf][nf][0];
                sOut[(co + 1) * 132 + px]     = acc[mf][nf][1];
                sOut[co * 132 + px + 8]       = acc[mf][nf][2];
                sOut[(co + 1) * 132 + px + 8] = acc[mf][nf][3];
            }
        }
        __syncthreads();

        #pragma unroll
        for (int k = 0; k < 8; k++) {
            int idx = tid + 256 * k;
            int co = idx >> 5;
            int q  = idx & 31;
            float4 v = *(float4*)&sOut[co * 132 + q * 4];
            *(float4*)(out + (((size_t)b * COUT + co) * HH + y) * WW + xh * 128 + q * 4) = v;
        }

        if (yy < 7) cpwait0();
        __syncthreads();
    }
}

// ---------------- launch ----------------
extern "C" void kernel_launch(void* const* d_in, const int* in_sizes, int n_in,
                              void* d_out, int out_size) {
    const float* input      = (const float*)d_in[0];
    const float* style      = (const float*)d_in[1];
    const float* weight     = (const float*)d_in[2];
    const float* mod_weight = (const float*)d_in[3];
    const float* mod_bias   = (const float*)d_in[4];
    float* out = (float*)d_out;

    cudaFuncSetAttribute(conv_kernel,
                         cudaFuncAttributeMaxDynamicSharedMemorySize, SMEM_TOTAL);

    style_mod_kernel<<<dim3(CIN, BATCH), 128>>>(style, mod_weight, mod_bias);
    demod_kernel<<<dim3(COUT, BATCH), 576>>>(weight);
    convert_kernel<<<dim3(8, HH, BATCH), 256>>>(input);
    pad_kernel<<<128, 256>>>();
    conv_kernel<<<dim3(2, 32, BATCH), 256, SMEM_TOTAL>>>(out);
}

// round 5
// speedup vs baseline: 5.6559x; 1.0362x over previous
#include <cuda_runtime.h>
#include <cuda_fp16.h>
#include <cstdint>
#include <math.h>

// ---------------- problem constants ----------------
#define BATCH 8
#define CIN   64
#define COUT  64
#define SDIM  512
#define HH    256
#define WW    256
#define TAPS  9

#define CONV_SCALE (1.0f / 24.0f)
#define MOD_SCALE  (0.04419417382415922f)
#define EPSV       (1e-8f)

#define PROWS 258   // padded rows: 1 zero row top & bottom

// ---------------- device scratch ----------------
__device__ float g_s[BATCH * CIN];
// transposed padded input fp16: [b][prow 0..257][x 0..255][ci 0..63]
__device__ __align__(16) __half g_in[(size_t)BATCH * PROWS * WW * CIN];
// demodulated weights fp16: [b][tap][co][ci]
__device__ __align__(16) __half g_wt[BATCH * TAPS * COUT * CIN];

// ---------------- helpers ----------------
__device__ __forceinline__ uint32_t smem_u32(const void* p) {
    uint32_t a;
    asm("{ .reg .u64 t; cvta.to.shared.u64 t, %1; cvt.u32.u64 %0, t; }" : "=r"(a) : "l"(p));
    return a;
}
__device__ __forceinline__ void ldsm4(uint32_t (&r)[4], uint32_t addr) {
    asm volatile("ldmatrix.sync.aligned.m8n8.x4.shared.b16 {%0,%1,%2,%3}, [%4];"
                 : "=r"(r[0]), "=r"(r[1]), "=r"(r[2]), "=r"(r[3]) : "r"(addr));
}
__device__ __forceinline__ void mma16816(float (&c)[4], const uint32_t (&a)[4],
                                         const uint32_t b0, const uint32_t b1) {
    asm volatile(
        "mma.sync.aligned.m16n8k16.row.col.f32.f16.f16.f32 "
        "{%0,%1,%2,%3}, {%4,%5,%6,%7}, {%8,%9}, {%0,%1,%2,%3};"
        : "+f"(c[0]), "+f"(c[1]), "+f"(c[2]), "+f"(c[3])
        : "r"(a[0]), "r"(a[1]), "r"(a[2]), "r"(a[3]), "r"(b0), "r"(b1));
}
__device__ __forceinline__ void cpasync16(uint32_t dst, const void* src) {
    asm volatile("cp.async.cg.shared.global [%0], [%1], 16;" :: "r"(dst), "l"(src) : "memory");
}
__device__ __forceinline__ void cpcommit() { asm volatile("cp.async.commit_group;" ::: "memory"); }
__device__ __forceinline__ void cpwait0()  { asm volatile("cp.async.wait_group 0;" ::: "memory"); }

__device__ __forceinline__ uint32_t sw128(uint32_t o) { return o ^ ((o >> 3) & 0x70u); }

// ---------------- kernel A: style modulation scalars ----------------
__global__ void style_mod_kernel(const float* __restrict__ style,
                                 const float* __restrict__ mw,
                                 const float* __restrict__ mb) {
    int ci = blockIdx.x;
    int b  = blockIdx.y;
    int tid = threadIdx.x;
    const float* sp = style + b * SDIM;
    const float* wp = mw + ci * SDIM;
    float sum = 0.f;
    for (int k = tid; k < SDIM; k += 128) sum += sp[k] * wp[k];
    #pragma unroll
    for (int off = 16; off > 0; off >>= 1)
        sum += __shfl_xor_sync(0xFFFFFFFFu, sum, off);
    __shared__ float red[4];
    if ((tid & 31) == 0) red[tid >> 5] = sum;
    __syncthreads();
    if (tid == 0)
        g_s[b * CIN + ci] = (red[0] + red[1] + red[2] + red[3]) * MOD_SCALE + mb[ci];
}

// ---------------- kernel B: demodulated weights -> fp16 --------------------
__global__ void demod_kernel(const float* __restrict__ w) {
    int co = blockIdx.x;
    int b  = blockIdx.y;
    int tid = threadIdx.x;      // (ci, tap)
    int ci  = tid / TAPS;
    int tap = tid - ci * TAPS;

    float val = CONV_SCALE * w[(co * CIN + ci) * TAPS + tap] * g_s[b * CIN + ci];

    __shared__ float red[576];
    red[tid] = val * val;
    __syncthreads();
    if (tid < 64) red[tid] += red[tid + 512];
    __syncthreads();
    for (int s = 256; s > 0; s >>= 1) {
        if (tid < s) red[tid] += red[tid + s];
        __syncthreads();
    }
    float vd = val * rsqrtf(red[0] + EPSV);
    g_wt[(((size_t)b * TAPS + tap) * COUT + co) * CIN + ci] = __float2half_rn(vd);
}

// ---------------- kernel C: convert + transpose input to fp16 --------------
__global__ void convert_kernel(const float* __restrict__ in) {
    __shared__ float s[64][33];
    const int tid = threadIdx.x;
    const int x0 = blockIdx.x * 32;
    const int y  = blockIdx.y;
    const int b  = blockIdx.z;

    for (int i = tid; i < 2048; i += 256) {
        int ci = i >> 5, x = i & 31;
        s[ci][x] = in[(((size_t)b * CIN + ci) * HH + y) * WW + x0 + x];
    }
    __syncthreads();

    const int x   = tid >> 3;
    const int ci0 = (tid & 7) << 3;
    uint32_t u[4];
    #pragma unroll
    for (int k = 0; k < 4; k++) {
        __half2 hp = __floats2half2_rn(s[ci0 + 2 * k][x], s[ci0 + 2 * k + 1][x]);
        u[k] = *reinterpret_cast<uint32_t*>(&hp);
    }
    size_t e = ((((size_t)b * PROWS + y + 1) * WW + x0 + x) * CIN + ci0) >> 3;
    ((uint4*)g_in)[e] = make_uint4(u[0], u[1], u[2], u[3]);
}

__global__ void pad_kernel() {
    int idx = blockIdx.x * 256 + threadIdx.x;      // 32768 uint4 total
    if (idx >= 32768) return;
    int b   = idx >> 12;
    int r   = (idx >> 11) & 1;
    int rem = idx & 2047;
    size_t row = (size_t)b * PROWS + (r ? (PROWS - 1) : 0);
    ((uint4*)g_in)[row * 2048 + rem] = make_uint4(0, 0, 0, 0);
}

// ---------------- kernel D: fp16 mma implicit conv, row-paired strips ------
// CTA = (xh, ychunk8, b): 128 px x 64 co x 8 output rows (4 row-pairs).
// 8 warps: 4 in M (32px) x 2 in N (32co).
// SMEM: W resident (72KB), 6-slot input row ring, 1-row output staging.
#define W_OFF      0u
#define W_BYTES    73728u
#define RING_OFF   73728u
#define ROW_STRIDE 17408u                       // 16640 used, 1024-aligned
#define OUT_OFF    (RING_OFF + 6u * ROW_STRIDE) // 178176
#define OUT_BYTES  (64u * 132u * 4u)            // 33792
#define SMEM_TOTAL (OUT_OFF + OUT_BYTES)        // 211968

__global__ __launch_bounds__(256, 1)
void conv_kernel(float* __restrict__ out) {
    extern __shared__ char smem[];
    const uint32_t sb = smem_u32(smem);
    const int tid  = threadIdx.x;
    const int wid  = tid >> 5;
    const int lane = tid & 31;
    const int xh = blockIdx.x;
    const int y0 = blockIdx.y * 8;
    const int b  = blockIdx.z;

    const int mwarp = wid & 3;
    const int nwarp = wid >> 2;
    const uint32_t px0 = mwarp * 32;
    const uint32_t co0 = nwarp * 32;

    const uint32_t arow = lane & 15;
    const uint32_t khA  = ((lane >> 4) & 1) * 16;
    const uint32_t brow = (lane & 7) | ((lane >> 1) & 8);
    const uint32_t khB  = ((lane >> 3) & 1) * 16;

    // ---- stage a padded input row into ring slot (cp.async, swizzled) ----
    auto stage_row = [&](int prow) {
        const uint32_t dstb = sb + RING_OFF + ((uint32_t)(prow % 6)) * ROW_STRIDE;
        const uint4* src = ((const uint4*)g_in) + ((size_t)(b * PROWS + prow) * 256) * 8;
        #pragma unroll
        for (int k = 0; k < 5; k++) {
            int idx = tid + 256 * k;            // 0..1039 (+pad)
            if (idx < 1040) {
                int px = idx >> 3;              // 0..129
                int g  = idx & 7;
                int gx = xh * 128 + px - 1;
                uint32_t dst = dstb + sw128((uint32_t)px * 128u + (uint32_t)g * 16u);
                if ((unsigned)gx < 256u) {
                    cpasync16(dst, src + (size_t)gx * 8 + g);
                } else {
                    *(uint4*)(smem + (dst - sb)) = make_uint4(0, 0, 0, 0);
                }
            }
        }
    };

    // ---- prologue: stage W + first 4 rows ----
    {
        const uint4* ws = ((const uint4*)g_wt) + (size_t)b * 4608;
        for (int j = tid; j < 4608; j += 256) {
            uint32_t o = (uint32_t)j << 4;
            cpasync16(sb + W_OFF + sw128(o), ws + j);
        }
    }
    stage_row(y0);
    stage_row(y0 + 1);
    stage_row(y0 + 2);
    stage_row(y0 + 3);
    cpcommit();
    cpwait0();
    __syncthreads();

    float* sOut = (float*)(smem + OUT_OFF);
    const int eg = lane >> 2;
    const int et = lane & 3;

    for (int p = 0; p < 4; p++) {
        const int y = y0 + 2 * p;
        if (p < 3) { stage_row(y + 4); stage_row(y + 5); cpcommit(); }

        // row slot base addresses for prows y..y+3
        uint32_t rowA[4];
        #pragma unroll
        for (int j = 0; j < 4; j++)
            rowA[j] = sb + RING_OFF + ((uint32_t)((y + j) % 6)) * ROW_STRIDE;

        float acc[2][2][4][4];   // [row][mf][nf][c]
        #pragma unroll
        for (int r = 0; r < 2; r++)
            #pragma unroll
            for (int mf = 0; mf < 2; mf++)
                #pragma unroll
                for (int nf = 0; nf < 4; nf++)
                    #pragma unroll
                    for (int c = 0; c < 4; c++) acc[r][mf][nf][c] = 0.f;

        for (int kc = 0; kc < 4; kc++) {
            const uint32_t kb = (uint32_t)kc * 32u;
            #pragma unroll
            for (int dx = 0; dx < 3; dx++) {
                // batched loads: 4 row-frags x 2 mf (A), 3 taps (W)
                uint32_t a[4][2][4];
                #pragma unroll
                for (int j = 0; j < 4; j++) {
                    #pragma unroll
                    for (int mf = 0; mf < 2; mf++) {
                        uint32_t o = (px0 + (uint32_t)mf * 16u + arow + (uint32_t)dx) * 128u
                                     + kb + khA;
                        ldsm4(a[j][mf], rowA[j] + sw128(o));
                    }
                }
                uint32_t wfr[3][4][2];
                #pragma unroll
                for (int dy = 0; dy < 3; dy++) {
                    const uint32_t tap = (uint32_t)(dy * 3 + dx);
                    #pragma unroll
                    for (int g = 0; g < 2; g++) {
                        uint32_t tmp[4];
                        uint32_t o = (tap * 64u + co0 + (uint32_t)g * 16u + brow) * 128u
                                     + kb + khB;
                        ldsm4(tmp, sb + W_OFF + sw128(o));
                        wfr[dy][g * 2][0]     = tmp[0]; wfr[dy][g * 2][1]     = tmp[1];
                        wfr[dy][g * 2 + 1][0] = tmp[2]; wfr[dy][g * 2 + 1][1] = tmp[3];
                    }
                }
                // 48 independent mma
                #pragma unroll
                for (int dy = 0; dy < 3; dy++)
                    #pragma unroll
                    for (int r = 0; r < 2; r++)
                        #pragma unroll
                        for (int mf = 0; mf < 2; mf++)
                            #pragma unroll
                            for (int nf = 0; nf < 4; nf++)
                                mma16816(acc[r][mf][nf], a[r + dy][mf],
                                         wfr[dy][nf][0], wfr[dy][nf][1]);
            }
        }

        // ---- epilogue: two rows through smem, coalesced float4 stores ----
        #pragma unroll
        for (int r = 0; r < 2; r++) {
            #pragma unroll
            for (int mf = 0; mf < 2; mf++) {
                #pragma unroll
                for (int nf = 0; nf < 4; nf++) {
                    int px = px0 + mf * 16 + eg;
                    int co = co0 + nf * 8 + 2 * et;
                    sOut[co * 132 + px]           = acc[r][mf][nf][0];
                    sOut[(co + 1) * 132 + px]     = acc[r][mf][nf][1];
                    sOut[co * 132 + px + 8]       = acc[r][mf][nf][2];
                    sOut[(co + 1) * 132 + px + 8] = acc[r][mf][nf][3];
                }
            }
            __syncthreads();
            #pragma unroll
            for (int k = 0; k < 8; k++) {
                int idx = tid + 256 * k;
                int co = idx >> 5;
                int q  = idx & 31;
                float4 v = *(float4*)&sOut[co * 132 + q * 4];
                *(float4*)(out + (((size_t)b * COUT + co) * HH + (y + r)) * WW
                           + xh * 128 + q * 4) = v;
            }
            __syncthreads();
        }

        if (p < 3) { cpwait0(); __syncthreads(); }
    }
}

// ---------------- launch ----------------
extern "C" void kernel_launch(void* const* d_in, const int* in_sizes, int n_in,
                              void* d_out, int out_size) {
    const float* input      = (const float*)d_in[0];
    const float* style      = (const float*)d_in[1];
    const float* weight     = (const float*)d_in[2];
    const float* mod_weight = (const float*)d_in[3];
    const float* mod_bias   = (const float*)d_in[4];
    float* out = (float*)d_out;

    cudaFuncSetAttribute(conv_kernel,
                         cudaFuncAttributeMaxDynamicSharedMemorySize, SMEM_TOTAL);

    style_mod_kernel<<<dim3(CIN, BATCH), 128>>>(style, mod_weight, mod_bias);
    demod_kernel<<<dim3(COUT, BATCH), 576>>>(weight);
    convert_kernel<<<dim3(8, HH, BATCH), 256>>>(input);
    pad_kernel<<<128, 256>>>();
    conv_kernel<<<dim3(2, 32, BATCH), 256, SMEM_TOTAL>>>(out);
}

// round 6
// speedup vs baseline: 6.9337x; 1.2259x over previous
#include <cuda_runtime.h>
#include <cuda_fp16.h>
#include <cstdint>
#include <math.h>

// ---------------- problem constants ----------------
#define BATCH 8
#define CIN   64
#define COUT  64
#define SDIM  512
#define HH    256
#define WW    256
#define TAPS  9

#define CONV_SCALE (1.0f / 24.0f)
#define MOD_SCALE  (0.04419417382415922f)
#define EPSV       (1e-8f)

// ---------------- device scratch ----------------
__device__ float g_s[BATCH * CIN];
// demodulated weights fp16: [b][tap][co][ci]
__device__ __align__(16) __half g_wt[BATCH * TAPS * COUT * CIN];

// ---------------- helpers ----------------
__device__ __forceinline__ uint32_t smem_u32(const void* p) {
    uint32_t a;
    asm("{ .reg .u64 t; cvta.to.shared.u64 t, %1; cvt.u32.u64 %0, t; }" : "=r"(a) : "l"(p));
    return a;
}
__device__ __forceinline__ void ldsm4(uint32_t (&r)[4], uint32_t addr) {
    asm volatile("ldmatrix.sync.aligned.m8n8.x4.shared.b16 {%0,%1,%2,%3}, [%4];"
                 : "=r"(r[0]), "=r"(r[1]), "=r"(r[2]), "=r"(r[3]) : "r"(addr));
}
__device__ __forceinline__ void mma16816(float (&c)[4], const uint32_t (&a)[4],
                                         const uint32_t b0, const uint32_t b1) {
    asm volatile(
        "mma.sync.aligned.m16n8k16.row.col.f32.f16.f16.f32 "
        "{%0,%1,%2,%3}, {%4,%5,%6,%7}, {%8,%9}, {%0,%1,%2,%3};"
        : "+f"(c[0]), "+f"(c[1]), "+f"(c[2]), "+f"(c[3])
        : "r"(a[0]), "r"(a[1]), "r"(a[2]), "r"(a[3]), "r"(b0), "r"(b1));
}
__device__ __forceinline__ void cpasync16(uint32_t dst, const void* src) {
    asm volatile("cp.async.cg.shared.global [%0], [%1], 16;" :: "r"(dst), "l"(src) : "memory");
}
__device__ __forceinline__ void cpcommit() { asm volatile("cp.async.commit_group;" ::: "memory"); }
__device__ __forceinline__ void cpwait0()  { asm volatile("cp.async.wait_group 0;" ::: "memory"); }

__device__ __forceinline__ uint32_t sw128(uint32_t o) { return o ^ ((o >> 3) & 0x70u); }

// ---------------- kernel A: style modulation scalars ----------------
__global__ void style_mod_kernel(const float* __restrict__ style,
                                 const float* __restrict__ mw,
                                 const float* __restrict__ mb) {
    int ci = blockIdx.x;
    int b  = blockIdx.y;
    int tid = threadIdx.x;
    const float* sp = style + b * SDIM;
    const float* wp = mw + ci * SDIM;
    float sum = 0.f;
    for (int k = tid; k < SDIM; k += 128) sum += sp[k] * wp[k];
    #pragma unroll
    for (int off = 16; off > 0; off >>= 1)
        sum += __shfl_xor_sync(0xFFFFFFFFu, sum, off);
    __shared__ float red[4];
    if ((tid & 31) == 0) red[tid >> 5] = sum;
    __syncthreads();
    if (tid == 0)
        g_s[b * CIN + ci] = (red[0] + red[1] + red[2] + red[3]) * MOD_SCALE + mb[ci];
}

// ---------------- kernel B: demodulated weights -> fp16 --------------------
__global__ void demod_kernel(const float* __restrict__ w) {
    int co = blockIdx.x;
    int b  = blockIdx.y;
    int tid = threadIdx.x;      // (ci, tap)
    int ci  = tid / TAPS;
    int tap = tid - ci * TAPS;

    float val = CONV_SCALE * w[(co * CIN + ci) * TAPS + tap] * g_s[b * CIN + ci];

    __shared__ float red[576];
    red[tid] = val * val;
    __syncthreads();
    if (tid < 64) red[tid] += red[tid + 512];
    __syncthreads();
    for (int s = 256; s > 0; s >>= 1) {
        if (tid < s) red[tid] += red[tid + s];
        __syncthreads();
    }
    float vd = val * rsqrtf(red[0] + EPSV);
    g_wt[(((size_t)b * TAPS + tap) * COUT + co) * CIN + ci] = __float2half_rn(vd);
}

// ---------------- kernel C: fused convert + fp16 mma implicit conv ---------
// CTA = (xh, ychunk8, b): 128 px x 64 co x 8 output rows (4 row-pairs).
// 8 warps: 4 in M (32px) x 2 in N (32co).
// SMEM: W resident (72KB); 6-slot fp16 input-row ring (converted in-kernel);
//       fp32 stage [64ci][140] shared with output-transpose buffer.
#define W_OFF      0u
#define W_BYTES    73728u
#define RING_OFF   73728u
#define ROW_STRIDE 16640u                        // 130 px x 128B
#define STAGE_OFF  (RING_OFF + 6u * ROW_STRIDE)  // 173568
#define STAGE_W    140                           // fp32 words per ci row (16B-aligned)
#define STAGE_BYTES (64u * STAGE_W * 4u)         // 35840
#define SMEM_TOTAL (STAGE_OFF + STAGE_BYTES)     // 209408

__global__ __launch_bounds__(256, 1)
void conv_kernel(const float* __restrict__ in, float* __restrict__ out) {
    extern __shared__ char smem[];
    const uint32_t sb = smem_u32(smem);
    const int tid  = threadIdx.x;
    const int wid  = tid >> 5;
    const int lane = tid & 31;
    const int xh = blockIdx.x;
    const int y0 = blockIdx.y * 8;
    const int b  = blockIdx.z;

    const int mwarp = wid & 3;
    const int nwarp = wid >> 2;
    const uint32_t px0 = mwarp * 32;
    const uint32_t co0 = nwarp * 32;

    const uint32_t arow = lane & 15;
    const uint32_t khA  = ((lane >> 4) & 1) * 16;
    const uint32_t brow = (lane & 7) | ((lane >> 1) & 8);
    const uint32_t khB  = ((lane >> 3) & 1) * 16;

    // ---- async-stage one raw fp32 input row into the stage buffer ----
    // stage[ci][word]: image px p lives at word p+3 (p = gx - (xh*128 - 1)).
    auto stage_async = [&](int iy) {
        if ((unsigned)iy >= 256u) return;
        #pragma unroll
        for (int it = 0; it < 9; it++) {
            int idx = tid + 256 * it;           // 64 ci x 34 chunks = 2176
            if (idx < 2176) {
                int ci = idx / 34;
                int c  = idx - ci * 34;
                int gx0 = xh * 128 - 4 + 4 * c;
                uint32_t doff = STAGE_OFF + (uint32_t)(ci * STAGE_W + 4 * c) * 4u;
                if ((unsigned)gx0 <= 252u) {
                    cpasync16(sb + doff,
                              in + (((size_t)(b * CIN + ci)) * HH + iy) * WW + gx0);
                } else {
                    *(uint4*)(smem + doff) = make_uint4(0, 0, 0, 0);
                }
            }
        }
    };

    // ---- convert staged fp32 row -> swizzled fp16 ring slot ----
    // warp = ci-group g, lane = px (conflict-free LDS, conflict-free STS.128)
    auto convert_row = [&](int iy) {
        const uint32_t roff = RING_OFF
            + ((uint32_t)((iy + 1 + 768) % 6)) * ROW_STRIDE;  // +768 keeps arg >=0
        const bool valid = ((unsigned)iy < 256u);
        const float* st = (const float*)(smem + STAGE_OFF);
        const int g = wid;
        #pragma unroll
        for (int it = 0; it < 5; it++) {
            int px = (it < 4) ? (it * 32 + lane) : (128 + lane);
            if (it == 4 && lane >= 2) break;
            float v[8];
            #pragma unroll
            for (int k = 0; k < 8; k++)
                v[k] = valid ? st[(g * 8 + k) * STAGE_W + px + 3] : 0.f;
            uint32_t u[4];
            #pragma unroll
            for (int k = 0; k < 4; k++) {
                __half2 hp = __floats2half2_rn(v[2 * k], v[2 * k + 1]);
                u[k] = *reinterpret_cast<uint32_t*>(&hp);
            }
            *(uint4*)(smem + roff + sw128((uint32_t)px * 128u + (uint32_t)g * 16u))
                = make_uint4(u[0], u[1], u[2], u[3]);
        }
    };

    // ---- prologue: W + first 4 input rows (y0-1 .. y0+2) ----
    {
        const uint4* ws = ((const uint4*)g_wt) + (size_t)b * 4608;
        for (int j = tid; j < 4608; j += 256) {
            uint32_t o = (uint32_t)j << 4;
            cpasync16(sb + W_OFF + sw128(o), ws + j);
        }
        cpcommit();
    }
    for (int j = 0; j < 4; j++) {
        int iy = y0 - 1 + j;
        stage_async(iy);
        cpcommit();
        cpwait0();
        __syncthreads();
        convert_row(iy);
        __syncthreads();
    }

    float* sOut = (float*)(smem + STAGE_OFF);
    const int eg = lane >> 2;
    const int et = lane & 3;

    for (int p = 0; p < 4; p++) {
        const int y = y0 + 2 * p;

        if (p < 3) { stage_async(y + 3); cpcommit(); }

        // ring slots for image rows y-1 .. y+2
        uint32_t rowA[4];
        #pragma unroll
        for (int j = 0; j < 4; j++)
            rowA[j] = sb + RING_OFF + ((uint32_t)((y + j) % 6)) * ROW_STRIDE;

        float acc[2][2][4][4];
        #pragma unroll
        for (int r = 0; r < 2; r++)
            #pragma unroll
            for (int mf = 0; mf < 2; mf++)
                #pragma unroll
                for (int nf = 0; nf < 4; nf++)
                    #pragma unroll
                    for (int c = 0; c < 4; c++) acc[r][mf][nf][c] = 0.f;

        for (int kc = 0; kc < 4; kc++) {
            const uint32_t kb = (uint32_t)kc * 32u;
            #pragma unroll
            for (int dx = 0; dx < 3; dx++) {
                uint32_t a[4][2][4];
                #pragma unroll
                for (int j = 0; j < 4; j++) {
                    #pragma unroll
                    for (int mf = 0; mf < 2; mf++) {
                        uint32_t o = (px0 + (uint32_t)mf * 16u + arow + (uint32_t)dx) * 128u
                                     + kb + khA;
                        ldsm4(a[j][mf], rowA[j] + sw128(o));
                    }
                }
                uint32_t wfr[3][4][2];
                #pragma unroll
                for (int dy = 0; dy < 3; dy++) {
                    const uint32_t tap = (uint32_t)(dy * 3 + dx);
                    #pragma unroll
                    for (int g = 0; g < 2; g++) {
                        uint32_t tmp[4];
                        uint32_t o = (tap * 64u + co0 + (uint32_t)g * 16u + brow) * 128u
                                     + kb + khB;
                        ldsm4(tmp, sb + W_OFF + sw128(o));
                        wfr[dy][g * 2][0]     = tmp[0]; wfr[dy][g * 2][1]     = tmp[1];
                        wfr[dy][g * 2 + 1][0] = tmp[2]; wfr[dy][g * 2 + 1][1] = tmp[3];
                    }
                }
                #pragma unroll
                for (int dy = 0; dy < 3; dy++)
                    #pragma unroll
                    for (int r = 0; r < 2; r++)
                        #pragma unroll
                        for (int mf = 0; mf < 2; mf++)
                            #pragma unroll
                            for (int nf = 0; nf < 4; nf++)
                                mma16816(acc[r][mf][nf], a[r + dy][mf],
                                         wfr[dy][nf][0], wfr[dy][nf][1]);
            }

            // mid-pair: consume staged row y+3, start staging row y+4
            if (kc == 1 && p < 3) {
                cpwait0();
                __syncthreads();
                convert_row(y + 3);            // -> slot (y+4)%6 (not in use)
                __syncthreads();
                stage_async(y + 4);
                cpcommit();
            }
        }

        // end of pair: consume staged row y+4
        if (p < 3) {
            cpwait0();
            __syncthreads();
            convert_row(y + 4);                // -> slot (y+5)%6 (not in use)
        }
        __syncthreads();

        // ---- epilogue: two rows through smem (stage reused), float4 stores --
        #pragma unroll
        for (int r = 0; r < 2; r++) {
            #pragma unroll
            for (int mf = 0; mf < 2; mf++) {
                #pragma unroll
                for (int nf = 0; nf < 4; nf++) {
                    int px = px0 + mf * 16 + eg;
                    int co = co0 + nf * 8 + 2 * et;
                    sOut[co * 132 + px]           = acc[r][mf][nf][0];
                    sOut[(co + 1) * 132 + px]     = acc[r][mf][nf][1];
                    sOut[co * 132 + px + 8]       = acc[r][mf][nf][2];
                    sOut[(co + 1) * 132 + px + 8] = acc[r][mf][nf][3];
                }
            }
            __syncthreads();
            #pragma unroll
            for (int k = 0; k < 8; k++) {
                int idx = tid + 256 * k;
                int co = idx >> 5;
                int q  = idx & 31;
                float4 v = *(float4*)&sOut[co * 132 + q * 4];
                *(float4*)(out + (((size_t)b * COUT + co) * HH + (y + r)) * WW
                           + xh * 128 + q * 4) = v;
            }
            __syncthreads();
        }
    }
}

// ---------------- launch ----------------
extern "C" void kernel_launch(void* const* d_in, const int* in_sizes, int n_in,
                              void* d_out, int out_size) {
    const float* input      = (const float*)d_in[0];
    const float* style      = (const float*)d_in[1];
    const float* weight     = (const float*)d_in[2];
    const float* mod_weight = (const float*)d_in[3];
    const float* mod_bias   = (const float*)d_in[4];
    float* out = (float*)d_out;

    cudaFuncSetAttribute(conv_kernel,
                         cudaFuncAttributeMaxDynamicSharedMemorySize, SMEM_TOTAL);

    style_mod_kernel<<<dim3(CIN, BATCH), 128>>>(style, mod_weight, mod_bias);
    demod_kernel<<<dim3(COUT, BATCH), 576>>>(weight);
    conv_kernel<<<dim3(2, 32, BATCH), 256, SMEM_TOTAL>>>(input, out);
}

// round 7
// speedup vs baseline: 7.0702x; 1.0197x over previous
#include <cuda_runtime.h>
#include <cuda_fp16.h>
#include <cstdint>
#include <math.h>

// ---------------- problem constants ----------------
#define BATCH 8
#define CIN   64
#define COUT  64
#define SDIM  512
#define HH    256
#define WW    256
#define TAPS  9

#define CONV_SCALE (1.0f / 24.0f)
#define MOD_SCALE  (0.04419417382415922f)
#define EPSV       (1e-8f)

// ---------------- device scratch ----------------
__device__ float g_s[BATCH * CIN];
// demodulated weights fp16: [b][tap][co][ci]
__device__ __align__(16) __half g_wt[BATCH * TAPS * COUT * CIN];

// ---------------- helpers ----------------
__device__ __forceinline__ uint32_t smem_u32(const void* p) {
    uint32_t a;
    asm("{ .reg .u64 t; cvta.to.shared.u64 t, %1; cvt.u32.u64 %0, t; }" : "=r"(a) : "l"(p));
    return a;
}
__device__ __forceinline__ void ldsm4(uint32_t (&r)[4], uint32_t addr) {
    asm volatile("ldmatrix.sync.aligned.m8n8.x4.shared.b16 {%0,%1,%2,%3}, [%4];"
                 : "=r"(r[0]), "=r"(r[1]), "=r"(r[2]), "=r"(r[3]) : "r"(addr));
}
__device__ __forceinline__ void mma16816(float (&c)[4], const uint32_t (&a)[4],
                                         const uint32_t b0, const uint32_t b1) {
    asm volatile(
        "mma.sync.aligned.m16n8k16.row.col.f32.f16.f16.f32 "
        "{%0,%1,%2,%3}, {%4,%5,%6,%7}, {%8,%9}, {%0,%1,%2,%3};"
        : "+f"(c[0]), "+f"(c[1]), "+f"(c[2]), "+f"(c[3])
        : "r"(a[0]), "r"(a[1]), "r"(a[2]), "r"(a[3]), "r"(b0), "r"(b1));
}
__device__ __forceinline__ void cpasync16(uint32_t dst, const void* src) {
    asm volatile("cp.async.cg.shared.global [%0], [%1], 16;" :: "r"(dst), "l"(src) : "memory");
}
__device__ __forceinline__ void cpcommit() { asm volatile("cp.async.commit_group;" ::: "memory"); }
__device__ __forceinline__ void cpwait0()  { asm volatile("cp.async.wait_group 0;" ::: "memory"); }

__device__ __forceinline__ uint32_t sw128(uint32_t o) { return o ^ ((o >> 3) & 0x70u); }

// ---------------- kernel A: style modulation scalars ----------------
__global__ void style_mod_kernel(const float* __restrict__ style,
                                 const float* __restrict__ mw,
                                 const float* __restrict__ mb) {
    int ci = blockIdx.x;
    int b  = blockIdx.y;
    int tid = threadIdx.x;
    const float* sp = style + b * SDIM;
    const float* wp = mw + ci * SDIM;
    float sum = 0.f;
    for (int k = tid; k < SDIM; k += 128) sum += sp[k] * wp[k];
    #pragma unroll
    for (int off = 16; off > 0; off >>= 1)
        sum += __shfl_xor_sync(0xFFFFFFFFu, sum, off);
    __shared__ float red[4];
    if ((tid & 31) == 0) red[tid >> 5] = sum;
    __syncthreads();
    if (tid == 0)
        g_s[b * CIN + ci] = (red[0] + red[1] + red[2] + red[3]) * MOD_SCALE + mb[ci];
}

// ---------------- kernel B: demodulated weights -> fp16 --------------------
__global__ void demod_kernel(const float* __restrict__ w) {
    int co = blockIdx.x;
    int b  = blockIdx.y;
    int tid = threadIdx.x;      // (ci, tap)
    int ci  = tid / TAPS;
    int tap = tid - ci * TAPS;

    float val = CONV_SCALE * w[(co * CIN + ci) * TAPS + tap] * g_s[b * CIN + ci];

    __shared__ float red[576];
    red[tid] = val * val;
    __syncthreads();
    if (tid < 64) red[tid] += red[tid + 512];
    __syncthreads();
    for (int s = 256; s > 0; s >>= 1) {
        if (tid < s) red[tid] += red[tid + s];
        __syncthreads();
    }
    float vd = val * rsqrtf(red[0] + EPSV);
    g_wt[(((size_t)b * TAPS + tap) * COUT + co) * CIN + ci] = __float2half_rn(vd);
}

// ---------------- kernel C: fused convert + fp16 mma implicit conv ---------
// CTA = (xq, ychunk8, b): 64 px x 64 co x 8 output rows (4 row-pairs).
// 8 warps: 2 in M (32px) x 4 in N (16co).
// SMEM: W resident (72KB); 6-slot fp16 ring (66px rows); 2-row fp32 stage
//       (shared with output-transpose buffer).
#define W_OFF      0u
#define W_BYTES    73728u
#define RING_OFF   73728u
#define ROW_STRIDE 9216u                         // 66px*128B=8448, pad to 9*1024
#define STAGE_OFF  (RING_OFF + 6u * ROW_STRIDE)  // 129024
#define STAGE_W    72                            // fp32 words per ci row
#define STAGE_ROW  (64u * STAGE_W * 4u)          // 18432 per staged row
#define SMEM_TOTAL (STAGE_OFF + 2u * STAGE_ROW)  // 165888

__global__ __launch_bounds__(256, 1)
void conv_kernel(const float* __restrict__ in, float* __restrict__ out) {
    extern __shared__ char smem[];
    const uint32_t sb = smem_u32(smem);
    const int tid  = threadIdx.x;
    const int wid  = tid >> 5;
    const int lane = tid & 31;
    const int x0 = blockIdx.x * 64;
    const int y0 = blockIdx.y * 8;
    const int b  = blockIdx.z;

    const int mwarp = wid & 1;
    const int nwarp = wid >> 1;
    const uint32_t px0 = mwarp * 32;
    const uint32_t co0 = nwarp * 16;

    const uint32_t arow = lane & 15;
    const uint32_t khA  = ((lane >> 4) & 1) * 16;
    const uint32_t brow = (lane & 7) | ((lane >> 1) & 8);
    const uint32_t khB  = ((lane >> 3) & 1) * 16;

    // ---- async-stage one raw fp32 input row into stage half ----
    // stage[half][ci][word]: image px p (= gx - (x0-1), 0..65) at word p+3.
    auto stage_async = [&](int iy, int half) {
        if ((unsigned)iy >= 256u) return;
        #pragma unroll
        for (int it = 0; it < 5; it++) {
            int idx = tid + 256 * it;           // 64 ci x 18 chunks = 1152
            if (idx < 1152) {
                int ci = idx / 18;
                int c  = idx - ci * 18;
                int gx0 = x0 - 4 + 4 * c;
                uint32_t doff = STAGE_OFF + (uint32_t)half * STAGE_ROW
                              + (uint32_t)(ci * STAGE_W + 4 * c) * 4u;
                if ((unsigned)gx0 <= 252u) {
                    cpasync16(sb + doff,
                              in + (((size_t)(b * CIN + ci)) * HH + iy) * WW + gx0);
                } else {
                    *(uint4*)(smem + doff) = make_uint4(0, 0, 0, 0);
                }
            }
        }
    };

    // ---- convert staged fp32 row -> swizzled fp16 ring slot ----
    auto convert_row = [&](int iy, int half) {
        const uint32_t roff = RING_OFF
            + ((uint32_t)((iy + 1 + 768) % 6)) * ROW_STRIDE;
        const bool valid = ((unsigned)iy < 256u);
        const float* st = (const float*)(smem + STAGE_OFF + half * STAGE_ROW);
        const int g = wid;
        #pragma unroll
        for (int it = 0; it < 3; it++) {
            int px = (it < 2) ? (it * 32 + lane) : (64 + lane);
            if (it == 2 && lane >= 2) break;
            float v[8];
            #pragma unroll
            for (int k = 0; k < 8; k++)
                v[k] = valid ? st[(g * 8 + k) * STAGE_W + px + 3] : 0.f;
            uint32_t u[4];
            #pragma unroll
            for (int k = 0; k < 4; k++) {
                __half2 hp = __floats2half2_rn(v[2 * k], v[2 * k + 1]);
                u[k] = *reinterpret_cast<uint32_t*>(&hp);
            }
            *(uint4*)(smem + roff + sw128((uint32_t)px * 128u + (uint32_t)g * 16u))
                = make_uint4(u[0], u[1], u[2], u[3]);
        }
    };

    // ---- prologue: W + rows y0-1..y0+2 in two 2-row rounds ----
    {
        const uint4* ws = ((const uint4*)g_wt) + (size_t)b * 4608;
        for (int j = tid; j < 4608; j += 256) {
            uint32_t o = (uint32_t)j << 4;
            cpasync16(sb + W_OFF + sw128(o), ws + j);
        }
        cpcommit();
    }
    #pragma unroll
    for (int rnd = 0; rnd < 2; rnd++) {
        stage_async(y0 - 1 + 2 * rnd, 0);
        stage_async(y0 + 2 * rnd, 1);
        cpcommit();
        cpwait0();
        __syncthreads();
        convert_row(y0 - 1 + 2 * rnd, 0);
        convert_row(y0 + 2 * rnd, 1);
        __syncthreads();
    }

    float* sOut = (float*)(smem + STAGE_OFF);    // [64co][72px] f32
    const int eg = lane >> 2;
    const int et = lane & 3;

    for (int p = 0; p < 4; p++) {
        const int y = y0 + 2 * p;

        if (p < 3) {
            stage_async(y + 3, 0);
            stage_async(y + 4, 1);
            cpcommit();
        }

        uint32_t rowA[4];
        #pragma unroll
        for (int j = 0; j < 4; j++)
            rowA[j] = sb + RING_OFF + ((uint32_t)((y + j) % 6)) * ROW_STRIDE;

        float acc[2][2][2][4];
        #pragma unroll
        for (int r = 0; r < 2; r++)
            #pragma unroll
            for (int mf = 0; mf < 2; mf++)
                #pragma unroll
                for (int nf = 0; nf < 2; nf++)
                    #pragma unroll
                    for (int c = 0; c < 4; c++) acc[r][mf][nf][c] = 0.f;

        for (int kc = 0; kc < 4; kc++) {
            const uint32_t kb = (uint32_t)kc * 32u;
            #pragma unroll
            for (int dx = 0; dx < 3; dx++) {
                uint32_t a[4][2][4];
                #pragma unroll
                for (int j = 0; j < 4; j++) {
                    #pragma unroll
                    for (int mf = 0; mf < 2; mf++) {
                        uint32_t o = (px0 + (uint32_t)mf * 16u + arow + (uint32_t)dx) * 128u
                                     + kb + khA;
                        ldsm4(a[j][mf], rowA[j] + sw128(o));
                    }
                }
                uint32_t wfr[3][2][2];
                #pragma unroll
                for (int dy = 0; dy < 3; dy++) {
                    const uint32_t tap = (uint32_t)(dy * 3 + dx);
                    uint32_t tmp[4];
                    uint32_t o = (tap * 64u + co0 + brow) * 128u + kb + khB;
                    ldsm4(tmp, sb + W_OFF + sw128(o));
                    wfr[dy][0][0] = tmp[0]; wfr[dy][0][1] = tmp[1];
                    wfr[dy][1][0] = tmp[2]; wfr[dy][1][1] = tmp[3];
                }
                #pragma unroll
                for (int dy = 0; dy < 3; dy++)
                    #pragma unroll
                    for (int r = 0; r < 2; r++)
                        #pragma unroll
                        for (int mf = 0; mf < 2; mf++)
                            #pragma unroll
                            for (int nf = 0; nf < 2; nf++)
                                mma16816(acc[r][mf][nf], a[r + dy][mf],
                                         wfr[dy][nf][0], wfr[dy][nf][1]);
            }
        }

        // consume staged rows -> ring (slots (y+4)%6, (y+5)%6: not in use)
        if (p < 3) {
            cpwait0();
            __syncthreads();
            convert_row(y + 3, 0);
            convert_row(y + 4, 1);
        }
        __syncthreads();

        // ---- epilogue: two rows via smem transpose (stage reused) ----
        #pragma unroll
        for (int r = 0; r < 2; r++) {
            #pragma unroll
            for (int mf = 0; mf < 2; mf++) {
                #pragma unroll
                for (int nf = 0; nf < 2; nf++) {
                    int px = px0 + mf * 16 + eg;
                    int co = co0 + nf * 8 + 2 * et;
                    sOut[co * 72 + px]           = acc[r][mf][nf][0];
                    sOut[(co + 1) * 72 + px]     = acc[r][mf][nf][1];
                    sOut[co * 72 + px + 8]       = acc[r][mf][nf][2];
                    sOut[(co + 1) * 72 + px + 8] = acc[r][mf][nf][3];
                }
            }
            __syncthreads();
            #pragma unroll
            for (int k = 0; k < 4; k++) {
                int idx = tid + 256 * k;            // 1024 float4
                int co = idx >> 4;
                int q  = idx & 15;
                float4 v = *(float4*)&sOut[co * 72 + q * 4];
                *(float4*)(out + (((size_t)b * COUT + co) * HH + (y + r)) * WW
                           + x0 + q * 4) = v;
            }
            __syncthreads();
        }
    }
}

// ---------------- launch ----------------
extern "C" void kernel_launch(void* const* d_in, const int* in_sizes, int n_in,
                              void* d_out, int out_size) {
    const float* input      = (const float*)d_in[0];
    const float* style      = (const float*)d_in[1];
    const float* weight     = (const float*)d_in[2];
    const float* mod_weight = (const float*)d_in[3];
    const float* mod_bias   = (const float*)d_in[4];
    float* out = (float*)d_out;

    cudaFuncSetAttribute(conv_kernel,
                         cudaFuncAttributeMaxDynamicSharedMemorySize, SMEM_TOTAL);

    style_mod_kernel<<<dim3(CIN, BATCH), 128>>>(style, mod_weight, mod_bias);
    demod_kernel<<<dim3(COUT, BATCH), 576>>>(weight);
    conv_kernel<<<dim3(4, 32, BATCH), 256, SMEM_TOTAL>>>(input, out);
}

// round 8
// speedup vs baseline: 7.7748x; 1.0997x over previous
#include <cuda_runtime.h>
#include <cuda_fp16.h>
#include <cstdint>
#include <math.h>

// ---------------- problem constants ----------------
#define BATCH 8
#define CIN   64
#define COUT  64
#define SDIM  512
#define HH    256
#define WW    256
#define TAPS  9

#define CONV_SCALE (1.0f / 24.0f)
#define MOD_SCALE  (0.04419417382415922f)
#define EPSV       (1e-8f)

// ---------------- device scratch ----------------
// demodulated weights fp16: [b][tap][co][ci]
__device__ __align__(16) __half g_wt[BATCH * TAPS * COUT * CIN];

// ---------------- helpers ----------------
__device__ __forceinline__ uint32_t smem_u32(const void* p) {
    uint32_t a;
    asm("{ .reg .u64 t; cvta.to.shared.u64 t, %1; cvt.u32.u64 %0, t; }" : "=r"(a) : "l"(p));
    return a;
}
__device__ __forceinline__ void ldsm4(uint32_t (&r)[4], uint32_t addr) {
    asm volatile("ldmatrix.sync.aligned.m8n8.x4.shared.b16 {%0,%1,%2,%3}, [%4];"
                 : "=r"(r[0]), "=r"(r[1]), "=r"(r[2]), "=r"(r[3]) : "r"(addr));
}
__device__ __forceinline__ void mma16816(float (&c)[4], const uint32_t (&a)[4],
                                         const uint32_t b0, const uint32_t b1) {
    asm volatile(
        "mma.sync.aligned.m16n8k16.row.col.f32.f16.f16.f32 "
        "{%0,%1,%2,%3}, {%4,%5,%6,%7}, {%8,%9}, {%0,%1,%2,%3};"
        : "+f"(c[0]), "+f"(c[1]), "+f"(c[2]), "+f"(c[3])
        : "r"(a[0]), "r"(a[1]), "r"(a[2]), "r"(a[3]), "r"(b0), "r"(b1));
}
__device__ __forceinline__ void cpasync16(uint32_t dst, const void* src) {
    asm volatile("cp.async.cg.shared.global [%0], [%1], 16;" :: "r"(dst), "l"(src) : "memory");
}
__device__ __forceinline__ void cpcommit() { asm volatile("cp.async.commit_group;" ::: "memory"); }
__device__ __forceinline__ void cpwait0()  { asm volatile("cp.async.wait_group 0;" ::: "memory"); }

__device__ __forceinline__ uint32_t sw128(uint32_t o) { return o ^ ((o >> 3) & 0x70u); }

// ---------------- kernel A: style modulation + demodulated fp16 weights ----
// block = (co, b), 576 threads.
__global__ void demod_kernel(const float* __restrict__ style,
                             const float* __restrict__ mw,
                             const float* __restrict__ mb,
                             const float* __restrict__ w) {
    int co = blockIdx.x;
    int b  = blockIdx.y;
    int tid = threadIdx.x;

    __shared__ float sdot[64];
    __shared__ float red[576];

    // phase 1: s[ci] = mod_scale * <style_b, mw_ci> + mb[ci] (8 threads per ci)
    if (tid < 512) {
        int ci = tid >> 3;
        int j  = tid & 7;
        const float* sp = style + b * SDIM;
        const float* wp = mw + ci * SDIM;
        float sum = 0.f;
        #pragma unroll 8
        for (int t = 0; t < 64; t++)
            sum += sp[j + 8 * t] * wp[j + 8 * t];
        sum += __shfl_xor_sync(0xFFFFFFFFu, sum, 4);
        sum += __shfl_xor_sync(0xFFFFFFFFu, sum, 2);
        sum += __shfl_xor_sync(0xFFFFFFFFu, sum, 1);
        if (j == 0) sdot[ci] = sum * MOD_SCALE + mb[ci];
    }
    __syncthreads();

    // phase 2: demodulation
    int ci  = tid / TAPS;
    int tap = tid - ci * TAPS;
    float val = CONV_SCALE * w[(co * CIN + ci) * TAPS + tap] * sdot[ci];

    red[tid] = val * val;
    __syncthreads();
    if (tid < 64) red[tid] += red[tid + 512];
    __syncthreads();
    for (int s = 256; s > 0; s >>= 1) {
        if (tid < s) red[tid] += red[tid + s];
        __syncthreads();
    }
    float vd = val * rsqrtf(red[0] + EPSV);
    g_wt[(((size_t)b * TAPS + tap) * COUT + co) * CIN + ci] = __float2half_rn(vd);
}

// ---------------- kernel B: persistent fused convert + fp16 mma conv -------
// 148 persistent CTAs; work unit = chunk (xq, ychunk8, b) of 64px x 64co x 8rows.
// Column-major chunk order -> consecutive chunks share the sliding row ring.
// 8 warps: 2 in M (32px) x 4 in N (16co).
#define W_OFF      0u
#define W_BYTES    73728u
#define RING_OFF   73728u
#define ROW_STRIDE 9216u
#define STAGE_OFF  (RING_OFF + 6u * ROW_STRIDE)  // 129024
#define STAGE_W    72
#define STAGE_ROW  (64u * STAGE_W * 4u)          // 18432
#define SMEM_TOTAL (STAGE_OFF + 2u * STAGE_ROW)  // 165888

#define NCTA       148
#define NCHUNKS    1024

__global__ __launch_bounds__(256, 1)
void conv_kernel(const float* __restrict__ in, float* __restrict__ out) {
    extern __shared__ char smem[];
    const uint32_t sb = smem_u32(smem);
    const int tid  = threadIdx.x;
    const int wid  = tid >> 5;
    const int lane = tid & 31;

    const int mwarp = wid & 1;
    const int nwarp = wid >> 1;
    const uint32_t px0 = mwarp * 32;
    const uint32_t co0 = nwarp * 16;

    const uint32_t arow = lane & 15;
    const uint32_t khA  = ((lane >> 4) & 1) * 16;
    const uint32_t brow = (lane & 7) | ((lane >> 1) & 8);
    const uint32_t khB  = ((lane >> 3) & 1) * 16;

    // chunk range: 136 CTAs x 7, 12 CTAs x 6
    const int cta = blockIdx.x;
    int c, cnt;
    if (cta < 136) { c = cta * 7;              cnt = 7; }
    else           { c = 952 + (cta - 136) * 6; cnt = 6; }

    float* sOut = (float*)(smem + STAGE_OFF);
    const int eg = lane >> 2;
    const int et = lane & 3;

    int last_b = -1;

    while (cnt > 0) {
        const int col    = c >> 5;          // 0..31
        const int within = c & 31;
        const int b  = col >> 2;
        const int x0 = (col & 3) * 64;
        const int run = min(cnt, 32 - within);
        const int y0r = within * 8;
        const int npairs = run * 4;

        // ---- staging lambdas bound to this run's (b, x0) ----
        auto stage_async = [&](int iy, int half) {
            if ((unsigned)iy >= 256u) return;
            #pragma unroll
            for (int it = 0; it < 5; it++) {
                int idx = tid + 256 * it;
                if (idx < 1152) {
                    int ci = idx / 18;
                    int cc = idx - ci * 18;
                    int gx0 = x0 - 4 + 4 * cc;
                    uint32_t doff = STAGE_OFF + (uint32_t)half * STAGE_ROW
                                  + (uint32_t)(ci * STAGE_W + 4 * cc) * 4u;
                    if ((unsigned)gx0 <= 252u) {
                        cpasync16(sb + doff,
                                  in + (((size_t)(b * CIN + ci)) * HH + iy) * WW + gx0);
                    } else {
                        *(uint4*)(smem + doff) = make_uint4(0, 0, 0, 0);
                    }
                }
            }
        };
        auto convert_row = [&](int iy, int half) {
            const uint32_t roff = RING_OFF
                + ((uint32_t)((iy + 1 + 768) % 6)) * ROW_STRIDE;
            const bool valid = ((unsigned)iy < 256u);
            const float* st = (const float*)(smem + STAGE_OFF + half * STAGE_ROW);
            const int g = wid;
            #pragma unroll
            for (int it = 0; it < 3; it++) {
                int px = (it < 2) ? (it * 32 + lane) : (64 + lane);
                if (it == 2 && lane >= 2) break;
                float v[8];
                #pragma unroll
                for (int k = 0; k < 8; k++)
                    v[k] = valid ? st[(g * 8 + k) * STAGE_W + px + 3] : 0.f;
                uint32_t u[4];
                #pragma unroll
                for (int k = 0; k < 4; k++) {
                    __half2 hp = __floats2half2_rn(v[2 * k], v[2 * k + 1]);
                    u[k] = *reinterpret_cast<uint32_t*>(&hp);
                }
                *(uint4*)(smem + roff + sw128((uint32_t)px * 128u + (uint32_t)g * 16u))
                    = make_uint4(u[0], u[1], u[2], u[3]);
            }
        };

        // ---- run prologue: W (if b changed) + prime rows y0r-1..y0r+2 ----
        if (b != last_b) {
            const uint4* ws = ((const uint4*)g_wt) + (size_t)b * 4608;
            for (int j = tid; j < 4608; j += 256) {
                uint32_t o = (uint32_t)j << 4;
                cpasync16(sb + W_OFF + sw128(o), ws + j);
            }
            cpcommit();
            last_b = b;
        }
        #pragma unroll
        for (int rnd = 0; rnd < 2; rnd++) {
            stage_async(y0r - 1 + 2 * rnd, 0);
            stage_async(y0r + 2 * rnd, 1);
            cpcommit();
            cpwait0();
            __syncthreads();
            convert_row(y0r - 1 + 2 * rnd, 0);
            convert_row(y0r + 2 * rnd, 1);
            __syncthreads();
        }

        // ---- continuous pair loop across the whole run ----
        for (int q = 0; q < npairs; q++) {
            const int y = y0r + 2 * q;
            const bool more = (q < npairs - 1);

            if (more) {
                stage_async(y + 3, 0);
                stage_async(y + 4, 1);
                cpcommit();
            }

            uint32_t rowA[4];
            #pragma unroll
            for (int j = 0; j < 4; j++)
                rowA[j] = sb + RING_OFF + ((uint32_t)((y + j) % 6)) * ROW_STRIDE;

            float acc[2][2][2][4];
            #pragma unroll
            for (int r = 0; r < 2; r++)
                #pragma unroll
                for (int mf = 0; mf < 2; mf++)
                    #pragma unroll
                    for (int nf = 0; nf < 2; nf++)
                        #pragma unroll
                        for (int cc = 0; cc < 4; cc++) acc[r][mf][nf][cc] = 0.f;

            for (int kc = 0; kc < 4; kc++) {
                const uint32_t kb = (uint32_t)kc * 32u;
                #pragma unroll
                for (int dx = 0; dx < 3; dx++) {
                    uint32_t a[4][2][4];
                    #pragma unroll
                    for (int j = 0; j < 4; j++) {
                        #pragma unroll
                        for (int mf = 0; mf < 2; mf++) {
                            uint32_t o = (px0 + (uint32_t)mf * 16u + arow + (uint32_t)dx)
                                         * 128u + kb + khA;
                            ldsm4(a[j][mf], rowA[j] + sw128(o));
                        }
                    }
                    uint32_t wfr[3][2][2];
                    #pragma unroll
                    for (int dy = 0; dy < 3; dy++) {
                        const uint32_t tap = (uint32_t)(dy * 3 + dx);
                        uint32_t tmp[4];
                        uint32_t o = (tap * 64u + co0 + brow) * 128u + kb + khB;
                        ldsm4(tmp, sb + W_OFF + sw128(o));
                        wfr[dy][0][0] = tmp[0]; wfr[dy][0][1] = tmp[1];
                        wfr[dy][1][0] = tmp[2]; wfr[dy][1][1] = tmp[3];
                    }
                    #pragma unroll
                    for (int dy = 0; dy < 3; dy++)
                        #pragma unroll
                        for (int r = 0; r < 2; r++)
                            #pragma unroll
                            for (int mf = 0; mf < 2; mf++)
                                #pragma unroll
                                for (int nf = 0; nf < 2; nf++)
                                    mma16816(acc[r][mf][nf], a[r + dy][mf],
                                             wfr[dy][nf][0], wfr[dy][nf][1]);
                }
            }

            if (more) {
                cpwait0();
                __syncthreads();
                convert_row(y + 3, 0);
                convert_row(y + 4, 1);
            }
            __syncthreads();

            // ---- epilogue: two rows via smem transpose (stage reused) ----
            #pragma unroll
            for (int r = 0; r < 2; r++) {
                #pragma unroll
                for (int mf = 0; mf < 2; mf++) {
                    #pragma unroll
                    for (int nf = 0; nf < 2; nf++) {
                        int px = px0 + mf * 16 + eg;
                        int co = co0 + nf * 8 + 2 * et;
                        sOut[co * 72 + px]           = acc[r][mf][nf][0];
                        sOut[(co + 1) * 72 + px]     = acc[r][mf][nf][1];
                        sOut[co * 72 + px + 8]       = acc[r][mf][nf][2];
                        sOut[(co + 1) * 72 + px + 8] = acc[r][mf][nf][3];
                    }
                }
                __syncthreads();
                #pragma unroll
                for (int k = 0; k < 4; k++) {
                    int idx = tid + 256 * k;
                    int co = idx >> 4;
                    int qq = idx & 15;
                    float4 v = *(float4*)&sOut[co * 72 + qq * 4];
                    *(float4*)(out + (((size_t)b * COUT + co) * HH + (y + r)) * WW
                               + x0 + qq * 4) = v;
                }
                __syncthreads();
            }
        }

        c   += run;
        cnt -= run;
    }
}

// ---------------- launch ----------------
extern "C" void kernel_launch(void* const* d_in, const int* in_sizes, int n_in,
                              void* d_out, int out_size) {
    const float* input      = (const float*)d_in[0];
    const float* style      = (const float*)d_in[1];
    const float* weight     = (const float*)d_in[2];
    const float* mod_weight = (const float*)d_in[3];
    const float* mod_bias   = (const float*)d_in[4];
    float* out = (float*)d_out;

    cudaFuncSetAttribute(conv_kernel,
                         cudaFuncAttributeMaxDynamicSharedMemorySize, SMEM_TOTAL);

    demod_kernel<<<dim3(COUT, BATCH), 576>>>(style, mod_weight, mod_bias, weight);
    conv_kernel<<<NCTA, 256, SMEM_TOTAL>>>(input, out);
}

// round 9
// speedup vs baseline: 7.9416x; 1.0215x over previous
#include <cuda_runtime.h>
#include <cuda_fp16.h>
#include <cstdint>
#include <math.h>

// ---------------- problem constants ----------------
#define BATCH 8
#define CIN   64
#define COUT  64
#define SDIM  512
#define HH    256
#define WW    256
#define TAPS  9

#define CONV_SCALE (1.0f / 24.0f)
#define MOD_SCALE  (0.04419417382415922f)
#define EPSV       (1e-8f)

// ---------------- device scratch ----------------
// demodulated weights fp16: [b][tap][co][ci]
__device__ __align__(16) __half g_wt[BATCH * TAPS * COUT * CIN];

// ---------------- helpers ----------------
__device__ __forceinline__ uint32_t smem_u32(const void* p) {
    uint32_t a;
    asm("{ .reg .u64 t; cvta.to.shared.u64 t, %1; cvt.u32.u64 %0, t; }" : "=r"(a) : "l"(p));
    return a;
}
__device__ __forceinline__ void ldsm4(uint32_t (&r)[4], uint32_t addr) {
    asm volatile("ldmatrix.sync.aligned.m8n8.x4.shared.b16 {%0,%1,%2,%3}, [%4];"
                 : "=r"(r[0]), "=r"(r[1]), "=r"(r[2]), "=r"(r[3]) : "r"(addr));
}
__device__ __forceinline__ void mma16816(float (&c)[4], const uint32_t (&a)[4],
                                         const uint32_t b0, const uint32_t b1) {
    asm volatile(
        "mma.sync.aligned.m16n8k16.row.col.f32.f16.f16.f32 "
        "{%0,%1,%2,%3}, {%4,%5,%6,%7}, {%8,%9}, {%0,%1,%2,%3};"
        : "+f"(c[0]), "+f"(c[1]), "+f"(c[2]), "+f"(c[3])
        : "r"(a[0]), "r"(a[1]), "r"(a[2]), "r"(a[3]), "r"(b0), "r"(b1));
}
__device__ __forceinline__ void cpasync16(uint32_t dst, const void* src) {
    asm volatile("cp.async.cg.shared.global [%0], [%1], 16;" :: "r"(dst), "l"(src) : "memory");
}
__device__ __forceinline__ void cpcommit() { asm volatile("cp.async.commit_group;" ::: "memory"); }
__device__ __forceinline__ void cpwait0()  { asm volatile("cp.async.wait_group 0;" ::: "memory"); }

__device__ __forceinline__ uint32_t sw128(uint32_t o) { return o ^ ((o >> 3) & 0x70u); }

// ---------------- kernel A: style modulation + demodulated fp16 weights ----
__global__ void demod_kernel(const float* __restrict__ style,
                             const float* __restrict__ mw,
                             const float* __restrict__ mb,
                             const float* __restrict__ w) {
    int co = blockIdx.x;
    int b  = blockIdx.y;
    int tid = threadIdx.x;

    __shared__ float sdot[64];
    __shared__ float red[576];

    if (tid < 512) {
        int ci = tid >> 3;
        int j  = tid & 7;
        const float* sp = style + b * SDIM;
        const float* wp = mw + ci * SDIM;
        float sum = 0.f;
        #pragma unroll 8
        for (int t = 0; t < 64; t++)
            sum += sp[j + 8 * t] * wp[j + 8 * t];
        sum += __shfl_xor_sync(0xFFFFFFFFu, sum, 4);
        sum += __shfl_xor_sync(0xFFFFFFFFu, sum, 2);
        sum += __shfl_xor_sync(0xFFFFFFFFu, sum, 1);
        if (j == 0) sdot[ci] = sum * MOD_SCALE + mb[ci];
    }
    __syncthreads();

    int ci  = tid / TAPS;
    int tap = tid - ci * TAPS;
    float val = CONV_SCALE * w[(co * CIN + ci) * TAPS + tap] * sdot[ci];

    red[tid] = val * val;
    __syncthreads();
    if (tid < 64) red[tid] += red[tid + 512];
    __syncthreads();
    for (int s = 256; s > 0; s >>= 1) {
        if (tid < s) red[tid] += red[tid + s];
        __syncthreads();
    }
    float vd = val * rsqrtf(red[0] + EPSV);
    g_wt[(((size_t)b * TAPS + tap) * COUT + co) * CIN + ci] = __float2half_rn(vd);
}

// ---------------- kernel B: persistent fused conv, 512 threads -------------
// Work unit = chunk (xh, y4chunk, b): 128px x 64co x 4 rows (2 pairs).
// 16 warps: 4 in M (32px) x 4 in N (16co). Column-major chunk order.
// SMEM: W resident (72KB); 6-slot fp16 ring (130px rows); 1-row fp32 stage
//       (shared with output-transpose buffer).
#define W_OFF      0u
#define W_BYTES    73728u
#define RING_OFF   73728u
#define ROW_STRIDE 16640u                        // 130 px x 128B
#define STAGE_OFF  (RING_OFF + 6u * ROW_STRIDE)  // 173568
#define STAGE_W    136                           // fp32 words per ci row
#define SMEM_TOTAL (STAGE_OFF + 64u * STAGE_W * 4u)   // 208384

#define NCTA       148
#define NCHUNKS    1024

__global__ __launch_bounds__(512, 1)
void conv_kernel(const float* __restrict__ in, float* __restrict__ out) {
    extern __shared__ char smem[];
    const uint32_t sb = smem_u32(smem);
    const int tid  = threadIdx.x;
    const int wid  = tid >> 5;
    const int lane = tid & 31;

    const int mwarp = wid & 3;
    const int nwarp = wid >> 2;
    const uint32_t px0 = mwarp * 32;
    const uint32_t co0 = nwarp * 16;

    const uint32_t arow = lane & 15;
    const uint32_t khA  = ((lane >> 4) & 1) * 16;
    const uint32_t brow = (lane & 7) | ((lane >> 1) & 8);
    const uint32_t khB  = ((lane >> 3) & 1) * 16;

    // chunk range: 136 CTAs x 7, 12 CTAs x 6  (1024 = 136*7 + 12*6)
    const int cta = blockIdx.x;
    int c, cnt;
    if (cta < 136) { c = cta * 7;               cnt = 7; }
    else           { c = 952 + (cta - 136) * 6; cnt = 6; }

    float* sOut = (float*)(smem + STAGE_OFF);    // [64co][132px] f32 (reuses stage)
    const int eg = lane >> 2;
    const int et = lane & 3;

    int last_b = -1;

    while (cnt > 0) {
        const int col    = c >> 6;          // 16 columns = b(8) x xh(2)
        const int within = c & 63;
        const int b  = col >> 1;
        const int x0 = (col & 1) * 128;
        const int run = min(cnt, 64 - within);
        const int y0r = within * 4;
        const int npairs = run * 2;

        // ---- stage one raw fp32 input row into the (single) stage buffer ----
        auto stage_async = [&](int iy) {
            if ((unsigned)iy >= 256u) return;
            #pragma unroll
            for (int it = 0; it < 5; it++) {
                int idx = tid + 512 * it;        // 64 ci x 34 chunks = 2176
                if (idx < 2176) {
                    int ci = idx / 34;
                    int cc = idx - ci * 34;
                    int gx0 = x0 - 4 + 4 * cc;
                    uint32_t doff = STAGE_OFF + (uint32_t)(ci * STAGE_W + 4 * cc) * 4u;
                    if ((unsigned)gx0 <= 252u) {
                        cpasync16(sb + doff,
                                  in + (((size_t)(b * CIN + ci)) * HH + iy) * WW + gx0);
                    } else {
                        *(uint4*)(smem + doff) = make_uint4(0, 0, 0, 0);
                    }
                }
            }
        };

        // ---- convert staged fp32 row -> swizzled fp16 ring slot ----
        auto convert_row = [&](int iy) {
            const uint32_t roff = RING_OFF
                + ((uint32_t)((iy + 1 + 768) % 6)) * ROW_STRIDE;
            const bool valid = ((unsigned)iy < 256u);
            const float* st = (const float*)(smem + STAGE_OFF);
            const int g = wid & 7;
            const int h = wid >> 3;
            #pragma unroll
            for (int it = 0; it < 3; it++) {
                int px = h * 64 + it * 32 + lane;
                if (it == 2) {
                    if (h == 0 || lane >= 2) break;
                    px = 128 + lane;
                }
                float v[8];
                #pragma unroll
                for (int k = 0; k < 8; k++)
                    v[k] = valid ? st[(g * 8 + k) * STAGE_W + px + 3] : 0.f;
                uint32_t u[4];
                #pragma unroll
                for (int k = 0; k < 4; k++) {
                    __half2 hp = __floats2half2_rn(v[2 * k], v[2 * k + 1]);
                    u[k] = *reinterpret_cast<uint32_t*>(&hp);
                }
                *(uint4*)(smem + roff + sw128((uint32_t)px * 128u + (uint32_t)g * 16u))
                    = make_uint4(u[0], u[1], u[2], u[3]);
            }
        };

        // ---- run prologue: W (if b changed) + prime rows y0r-1..y0r+2 ----
        if (b != last_b) {
            const uint4* ws = ((const uint4*)g_wt) + (size_t)b * 4608;
            for (int j = tid; j < 4608; j += 512) {
                uint32_t o = (uint32_t)j << 4;
                cpasync16(sb + W_OFF + sw128(o), ws + j);
            }
            cpcommit();
            last_b = b;
        }
        #pragma unroll 1
        for (int rnd = 0; rnd < 4; rnd++) {
            stage_async(y0r - 1 + rnd);
            cpcommit();
            cpwait0();
            __syncthreads();
            convert_row(y0r - 1 + rnd);
            __syncthreads();
        }

        // ---- continuous pair loop across the whole run ----
        for (int q = 0; q < npairs; q++) {
            const int y = y0r + 2 * q;
            const bool more = (q < npairs - 1);

            if (more) { stage_async(y + 3); cpcommit(); }

            uint32_t rowA[4];
            #pragma unroll
            for (int j = 0; j < 4; j++)
                rowA[j] = sb + RING_OFF + ((uint32_t)((y + j) % 6)) * ROW_STRIDE;

            float acc[2][2][2][4];
            #pragma unroll
            for (int r = 0; r < 2; r++)
                #pragma unroll
                for (int mf = 0; mf < 2; mf++)
                    #pragma unroll
                    for (int nf = 0; nf < 2; nf++)
                        #pragma unroll
                        for (int cc = 0; cc < 4; cc++) acc[r][mf][nf][cc] = 0.f;

            for (int kc = 0; kc < 4; kc++) {
                const uint32_t kb = (uint32_t)kc * 32u;
                #pragma unroll
                for (int dx = 0; dx < 3; dx++) {
                    uint32_t a[4][2][4];
                    #pragma unroll
                    for (int j = 0; j < 4; j++) {
                        #pragma unroll
                        for (int mf = 0; mf < 2; mf++) {
                            uint32_t o = (px0 + (uint32_t)mf * 16u + arow + (uint32_t)dx)
                                         * 128u + kb + khA;
                            ldsm4(a[j][mf], rowA[j] + sw128(o));
                        }
                    }
                    uint32_t wfr[3][2][2];
                    #pragma unroll
                    for (int dy = 0; dy < 3; dy++) {
                        const uint32_t tap = (uint32_t)(dy * 3 + dx);
                        uint32_t tmp[4];
                        uint32_t o = (tap * 64u + co0 + brow) * 128u + kb + khB;
                        ldsm4(tmp, sb + W_OFF + sw128(o));
                        wfr[dy][0][0] = tmp[0]; wfr[dy][0][1] = tmp[1];
                        wfr[dy][1][0] = tmp[2]; wfr[dy][1][1] = tmp[3];
                    }
                    #pragma unroll
                    for (int dy = 0; dy < 3; dy++)
                        #pragma unroll
                        for (int r = 0; r < 2; r++)
                            #pragma unroll
                            for (int mf = 0; mf < 2; mf++)
                                #pragma unroll
                                for (int nf = 0; nf < 2; nf++)
                                    mma16816(acc[r][mf][nf], a[r + dy][mf],
                                             wfr[dy][nf][0], wfr[dy][nf][1]);
                }

                // mid-pair: consume staged row y+3, start staging row y+4
                if (kc == 1 && more) {
                    cpwait0();
                    __syncthreads();
                    convert_row(y + 3);         // -> slot (y+4)%6 (free)
                    __syncthreads();
                    stage_async(y + 4);
                    cpcommit();
                }
            }

            if (more) {
                cpwait0();
                __syncthreads();
                convert_row(y + 4);             // -> slot (y+5)%6 (free)
            }
            __syncthreads();

            // ---- epilogue: two rows via smem transpose (stage reused) ----
            #pragma unroll
            for (int r = 0; r < 2; r++) {
                #pragma unroll
                for (int mf = 0; mf < 2; mf++) {
                    #pragma unroll
                    for (int nf = 0; nf < 2; nf++) {
                        int px = px0 + mf * 16 + eg;
                        int co = co0 + nf * 8 + 2 * et;
                        sOut[co * 132 + px]           = acc[r][mf][nf][0];
                        sOut[(co + 1) * 132 + px]     = acc[r][mf][nf][1];
                        sOut[co * 132 + px + 8]       = acc[r][mf][nf][2];
                        sOut[(co + 1) * 132 + px + 8] = acc[r][mf][nf][3];
                    }
                }
                __syncthreads();
                #pragma unroll
                for (int k = 0; k < 4; k++) {
                    int idx = tid + 512 * k;        // 2048 float4
                    int co = idx >> 5;
                    int qq = idx & 31;
                    float4 v = *(float4*)&sOut[co * 132 + qq * 4];
                    *(float4*)(out + (((size_t)b * COUT + co) * HH + (y + r)) * WW
                               + x0 + qq * 4) = v;
                }
                __syncthreads();
            }
        }

        c   += run;
        cnt -= run;
    }
}

// ---------------- launch ----------------
extern "C" void kernel_launch(void* const* d_in, const int* in_sizes, int n_in,
                              void* d_out, int out_size) {
    const float* input      = (const float*)d_in[0];
    const float* style      = (const float*)d_in[1];
    const float* weight     = (const float*)d_in[2];
    const float* mod_weight = (const float*)d_in[3];
    const float* mod_bias   = (const float*)d_in[4];
    float* out = (float*)d_out;

    cudaFuncSetAttribute(conv_kernel,
                         cudaFuncAttributeMaxDynamicSharedMemorySize, SMEM_TOTAL);

    demod_kernel<<<dim3(COUT, BATCH), 576>>>(style, mod_weight, mod_bias, weight);
    conv_kernel<<<NCTA, 512, SMEM_TOTAL>>>(input, out);
}

// round 10
// speedup vs baseline: 7.9555x; 1.0018x over previous
#include <cuda_runtime.h>
#include <cuda_fp16.h>
#include <cstdint>
#include <math.h>

// ---------------- problem constants ----------------
#define BATCH 8
#define CIN   64
#define COUT  64
#define SDIM  512
#define HH    256
#define WW    256
#define TAPS  9

#define CONV_SCALE (1.0f / 24.0f)
#define MOD_SCALE  (0.04419417382415922f)
#define EPSV       (1e-8f)

// ---------------- device scratch ----------------
// demodulated weights fp16: [b][tap][co][ci]
__device__ __align__(16) __half g_wt[BATCH * TAPS * COUT * CIN];

// ---------------- helpers ----------------
__device__ __forceinline__ uint32_t smem_u32(const void* p) {
    uint32_t a;
    asm("{ .reg .u64 t; cvta.to.shared.u64 t, %1; cvt.u32.u64 %0, t; }" : "=r"(a) : "l"(p));
    return a;
}
__device__ __forceinline__ void ldsm4(uint32_t (&r)[4], uint32_t addr) {
    asm volatile("ldmatrix.sync.aligned.m8n8.x4.shared.b16 {%0,%1,%2,%3}, [%4];"
                 : "=r"(r[0]), "=r"(r[1]), "=r"(r[2]), "=r"(r[3]) : "r"(addr));
}
__device__ __forceinline__ void mma16816(float (&c)[4], const uint32_t (&a)[4],
                                         const uint32_t b0, const uint32_t b1) {
    asm volatile(
        "mma.sync.aligned.m16n8k16.row.col.f32.f16.f16.f32 "
        "{%0,%1,%2,%3}, {%4,%5,%6,%7}, {%8,%9}, {%0,%1,%2,%3};"
        : "+f"(c[0]), "+f"(c[1]), "+f"(c[2]), "+f"(c[3])
        : "r"(a[0]), "r"(a[1]), "r"(a[2]), "r"(a[3]), "r"(b0), "r"(b1));
}
__device__ __forceinline__ void cpasync16(uint32_t dst, const void* src) {
    asm volatile("cp.async.cg.shared.global [%0], [%1], 16;" :: "r"(dst), "l"(src) : "memory");
}
__device__ __forceinline__ void cpcommit() { asm volatile("cp.async.commit_group;" ::: "memory"); }
__device__ __forceinline__ void cpwait0()  { asm volatile("cp.async.wait_group 0;" ::: "memory"); }

__device__ __forceinline__ uint32_t sw128(uint32_t o) { return o ^ ((o >> 3) & 0x70u); }

// ---------------- kernel A: style modulation + demodulated fp16 weights ----
__global__ void demod_kernel(const float* __restrict__ style,
                             const float* __restrict__ mw,
                             const float* __restrict__ mb,
                             const float* __restrict__ w) {
    int co = blockIdx.x;
    int b  = blockIdx.y;
    int tid = threadIdx.x;

    __shared__ float sdot[64];
    __shared__ float red[576];

    if (tid < 512) {
        int ci = tid >> 3;
        int j  = tid & 7;
        const float* sp = style + b * SDIM;
        const float* wp = mw + ci * SDIM;
        float sum = 0.f;
        #pragma unroll 8
        for (int t = 0; t < 64; t++)
            sum += sp[j + 8 * t] * wp[j + 8 * t];
        sum += __shfl_xor_sync(0xFFFFFFFFu, sum, 4);
        sum += __shfl_xor_sync(0xFFFFFFFFu, sum, 2);
        sum += __shfl_xor_sync(0xFFFFFFFFu, sum, 1);
        if (j == 0) sdot[ci] = sum * MOD_SCALE + mb[ci];
    }
    __syncthreads();

    int ci  = tid / TAPS;
    int tap = tid - ci * TAPS;
    float val = CONV_SCALE * w[(co * CIN + ci) * TAPS + tap] * sdot[ci];

    red[tid] = val * val;
    __syncthreads();
    if (tid < 64) red[tid] += red[tid + 512];
    __syncthreads();
    for (int s = 256; s > 0; s >>= 1) {
        if (tid < s) red[tid] += red[tid + s];
        __syncthreads();
    }
    float vd = val * rsqrtf(red[0] + EPSV);
    g_wt[(((size_t)b * TAPS + tap) * COUT + co) * CIN + ci] = __float2half_rn(vd);
}

// ---------------- kernel B: persistent fused conv, 512 threads -------------
// Work unit = chunk (xh, y4chunk, b): 128px x 64co x 4 rows (2 pairs).
// 16 warps: 4 in M (32px) x 4 in N (16co). Column-major chunk order.
// Warp-staggered dx order de-phases LDSM bursts from MMA bursts across warps.
#define W_OFF      0u
#define W_BYTES    73728u
#define RING_OFF   73728u
#define ROW_STRIDE 16640u                        // 130 px x 128B
#define STAGE_OFF  (RING_OFF + 6u * ROW_STRIDE)  // 173568
#define STAGE_W    136                           // fp32 words per ci row
#define SMEM_TOTAL (STAGE_OFF + 64u * STAGE_W * 4u)   // 208384

#define NCTA       148

__global__ __launch_bounds__(512, 1)
void conv_kernel(const float* __restrict__ in, float* __restrict__ out) {
    extern __shared__ char smem[];
    const uint32_t sb = smem_u32(smem);
    const int tid  = threadIdx.x;
    const int wid  = tid >> 5;
    const int lane = tid & 31;

    const int mwarp = wid & 3;
    const int nwarp = wid >> 2;
    const uint32_t px0 = mwarp * 32;
    const uint32_t co0 = nwarp * 16;
    const int woff = wid % 3;          // dx stagger per warp

    const uint32_t arow = lane & 15;
    const uint32_t khA  = ((lane >> 4) & 1) * 16;
    const uint32_t brow = (lane & 7) | ((lane >> 1) & 8);
    const uint32_t khB  = ((lane >> 3) & 1) * 16;

    // chunk range: 136 CTAs x 7, 12 CTAs x 6  (1024 = 136*7 + 12*6)
    const int cta = blockIdx.x;
    int c, cnt;
    if (cta < 136) { c = cta * 7;               cnt = 7; }
    else           { c = 952 + (cta - 136) * 6; cnt = 6; }

    float* sOut = (float*)(smem + STAGE_OFF);    // [64co][132px] f32 (reuses stage)
    const int eg = lane >> 2;
    const int et = lane & 3;

    int last_b = -1;

    while (cnt > 0) {
        const int col    = c >> 6;          // 16 columns = b(8) x xh(2)
        const int within = c & 63;
        const int b  = col >> 1;
        const int x0 = (col & 1) * 128;
        const int run = min(cnt, 64 - within);
        const int y0r = within * 4;
        const int npairs = run * 2;

        // ---- stage one raw fp32 input row into the (single) stage buffer ----
        auto stage_async = [&](int iy) {
            if ((unsigned)iy >= 256u) return;
            #pragma unroll
            for (int it = 0; it < 5; it++) {
                int idx = tid + 512 * it;        // 64 ci x 34 chunks = 2176
                if (idx < 2176) {
                    int ci = idx / 34;
                    int cc = idx - ci * 34;
                    int gx0 = x0 - 4 + 4 * cc;
                    uint32_t doff = STAGE_OFF + (uint32_t)(ci * STAGE_W + 4 * cc) * 4u;
                    if ((unsigned)gx0 <= 252u) {
                        cpasync16(sb + doff,
                                  in + (((size_t)(b * CIN + ci)) * HH + iy) * WW + gx0);
                    } else {
                        *(uint4*)(smem + doff) = make_uint4(0, 0, 0, 0);
                    }
                }
            }
        };

        // ---- convert staged fp32 row -> swizzled fp16 ring slot ----
        auto convert_row = [&](int iy) {
            const uint32_t roff = RING_OFF
                + ((uint32_t)((iy + 1 + 768) % 6)) * ROW_STRIDE;
            const bool valid = ((unsigned)iy < 256u);
            const float* st = (const float*)(smem + STAGE_OFF);
            const int g = wid & 7;
            const int h = wid >> 3;
            #pragma unroll
            for (int it = 0; it < 3; it++) {
                int px = h * 64 + it * 32 + lane;
                if (it == 2) {
                    if (h == 0 || lane >= 2) break;
                    px = 128 + lane;
                }
                float v[8];
                #pragma unroll
                for (int k = 0; k < 8; k++)
                    v[k] = valid ? st[(g * 8 + k) * STAGE_W + px + 3] : 0.f;
                uint32_t u[4];
                #pragma unroll
                for (int k = 0; k < 4; k++) {
                    __half2 hp = __floats2half2_rn(v[2 * k], v[2 * k + 1]);
                    u[k] = *reinterpret_cast<uint32_t*>(&hp);
                }
                *(uint4*)(smem + roff + sw128((uint32_t)px * 128u + (uint32_t)g * 16u))
                    = make_uint4(u[0], u[1], u[2], u[3]);
            }
        };

        // ---- run prologue: W (if b changed) + prime rows y0r-1..y0r+2 ----
        if (b != last_b) {
            const uint4* ws = ((const uint4*)g_wt) + (size_t)b * 4608;
            for (int j = tid; j < 4608; j += 512) {
                uint32_t o = (uint32_t)j << 4;
                cpasync16(sb + W_OFF + sw128(o), ws + j);
            }
            cpcommit();
            last_b = b;
        }
        #pragma unroll 1
        for (int rnd = 0; rnd < 4; rnd++) {
            stage_async(y0r - 1 + rnd);
            cpcommit();
            cpwait0();
            __syncthreads();
            convert_row(y0r - 1 + rnd);
            __syncthreads();
        }

        // ---- continuous pair loop across the whole run ----
        for (int q = 0; q < npairs; q++) {
            const int y = y0r + 2 * q;
            const bool more = (q < npairs - 1);

            if (more) { stage_async(y + 3); cpcommit(); }

            uint32_t rowA[4];
            #pragma unroll
            for (int j = 0; j < 4; j++)
                rowA[j] = sb + RING_OFF + ((uint32_t)((y + j) % 6)) * ROW_STRIDE;

            float acc[2][2][2][4];
            #pragma unroll
            for (int r = 0; r < 2; r++)
                #pragma unroll
                for (int mf = 0; mf < 2; mf++)
                    #pragma unroll
                    for (int nf = 0; nf < 2; nf++)
                        #pragma unroll
                        for (int cc = 0; cc < 4; cc++) acc[r][mf][nf][cc] = 0.f;

            for (int kc = 0; kc < 4; kc++) {
                const uint32_t kb = (uint32_t)kc * 32u;
                #pragma unroll
                for (int dxi = 0; dxi < 3; dxi++) {
                    int dxs = dxi + woff;
                    const uint32_t dx = (uint32_t)(dxs >= 3 ? dxs - 3 : dxs);

                    // W fragments first (3 ldsm)
                    uint32_t wfr[3][2][2];
                    #pragma unroll
                    for (int dy = 0; dy < 3; dy++) {
                        const uint32_t tap = (uint32_t)(dy * 3) + dx;
                        uint32_t tmp[4];
                        uint32_t o = (tap * 64u + co0 + brow) * 128u + kb + khB;
                        ldsm4(tmp, sb + W_OFF + sw128(o));
                        wfr[dy][0][0] = tmp[0]; wfr[dy][0][1] = tmp[1];
                        wfr[dy][1][0] = tmp[2]; wfr[dy][1][1] = tmp[3];
                    }
                    // A fragments (8 ldsm)
                    uint32_t a[4][2][4];
                    #pragma unroll
                    for (int j = 0; j < 4; j++) {
                        #pragma unroll
                        for (int mf = 0; mf < 2; mf++) {
                            uint32_t o = (px0 + (uint32_t)mf * 16u + arow + dx)
                                         * 128u + kb + khA;
                            ldsm4(a[j][mf], rowA[j] + sw128(o));
                        }
                    }
                    // 24 mma
                    #pragma unroll
                    for (int dy = 0; dy < 3; dy++)
                        #pragma unroll
                        for (int r = 0; r < 2; r++)
                            #pragma unroll
                            for (int mf = 0; mf < 2; mf++)
                                #pragma unroll
                                for (int nf = 0; nf < 2; nf++)
                                    mma16816(acc[r][mf][nf], a[r + dy][mf],
                                             wfr[dy][nf][0], wfr[dy][nf][1]);
                }

                // mid-pair: consume staged row y+3, start staging row y+4
                if (kc == 1 && more) {
                    cpwait0();
                    __syncthreads();
                    convert_row(y + 3);         // -> slot (y+4)%6 (free)
                    __syncthreads();
                    stage_async(y + 4);
                    cpcommit();
                }
            }

            if (more) {
                cpwait0();
                __syncthreads();
                convert_row(y + 4);             // -> slot (y+5)%6 (free)
            }
            __syncthreads();

            // ---- epilogue: two rows via smem transpose (stage reused) ----
            #pragma unroll
            for (int r = 0; r < 2; r++) {
                #pragma unroll
                for (int mf = 0; mf < 2; mf++) {
                    #pragma unroll
                    for (int nf = 0; nf < 2; nf++) {
                        int px = px0 + mf * 16 + eg;
                        int co = co0 + nf * 8 + 2 * et;
                        sOut[co * 132 + px]           = acc[r][mf][nf][0];
                        sOut[(co + 1) * 132 + px]     = acc[r][mf][nf][1];
                        sOut[co * 132 + px + 8]       = acc[r][mf][nf][2];
                        sOut[(co + 1) * 132 + px + 8] = acc[r][mf][nf][3];
                    }
                }
                __syncthreads();
                #pragma unroll
                for (int k = 0; k < 4; k++) {
                    int idx = tid + 512 * k;        // 2048 float4
                    int co = idx >> 5;
                    int qq = idx & 31;
                    float4 v = *(float4*)&sOut[co * 132 + qq * 4];
                    *(float4*)(out + (((size_t)b * COUT + co) * HH + (y + r)) * WW
                               + x0 + qq * 4) = v;
                }
                __syncthreads();
            }
        }

        c   += run;
        cnt -= run;
    }
}

// ---------------- launch ----------------
extern "C" void kernel_launch(void* const* d_in, const int* in_sizes, int n_in,
                              void* d_out, int out_size) {
    const float* input      = (const float*)d_in[0];
    const float* style      = (const float*)d_in[1];
    const float* weight     = (const float*)d_in[2];
    const float* mod_weight = (const float*)d_in[3];
    const float* mod_bias   = (const float*)d_in[4];
    float* out = (float*)d_out;

    cudaFuncSetAttribute(conv_kernel,
                         cudaFuncAttributeMaxDynamicSharedMemorySize, SMEM_TOTAL);

    demod_kernel<<<dim3(COUT, BATCH), 576>>>(style, mod_weight, mod_bias, weight);
    conv_kernel<<<NCTA, 512, SMEM_TOTAL>>>(input, out);
}

// round 11
// speedup vs baseline: 8.0544x; 1.0124x over previous
#include <cuda_runtime.h>
#include <cuda_fp16.h>
#include <cstdint>
#include <math.h>

// ---------------- problem constants ----------------
#define BATCH 8
#define CIN   64
#define COUT  64
#define SDIM  512
#define HH    256
#define WW    256
#define TAPS  9

#define CONV_SCALE (1.0f / 24.0f)
#define MOD_SCALE  (0.04419417382415922f)
#define EPSV       (1e-8f)

// ---------------- device scratch ----------------
// demodulated weights fp16: [b][tap][co][ci]
__device__ __align__(16) __half g_wt[BATCH * TAPS * COUT * CIN];

// ---------------- helpers ----------------
__device__ __forceinline__ uint32_t smem_u32(const void* p) {
    uint32_t a;
    asm("{ .reg .u64 t; cvta.to.shared.u64 t, %1; cvt.u32.u64 %0, t; }" : "=r"(a) : "l"(p));
    return a;
}
__device__ __forceinline__ void ldsm4(uint32_t (&r)[4], uint32_t addr) {
    asm volatile("ldmatrix.sync.aligned.m8n8.x4.shared.b16 {%0,%1,%2,%3}, [%4];"
                 : "=r"(r[0]), "=r"(r[1]), "=r"(r[2]), "=r"(r[3]) : "r"(addr));
}
__device__ __forceinline__ void mma16816(float (&c)[4], const uint32_t (&a)[4],
                                         const uint32_t b0, const uint32_t b1) {
    asm volatile(
        "mma.sync.aligned.m16n8k16.row.col.f32.f16.f16.f32 "
        "{%0,%1,%2,%3}, {%4,%5,%6,%7}, {%8,%9}, {%0,%1,%2,%3};"
        : "+f"(c[0]), "+f"(c[1]), "+f"(c[2]), "+f"(c[3])
        : "r"(a[0]), "r"(a[1]), "r"(a[2]), "r"(a[3]), "r"(b0), "r"(b1));
}
__device__ __forceinline__ void cpasync16(uint32_t dst, const void* src) {
    asm volatile("cp.async.cg.shared.global [%0], [%1], 16;" :: "r"(dst), "l"(src) : "memory");
}
__device__ __forceinline__ void cpcommit() { asm volatile("cp.async.commit_group;" ::: "memory"); }
__device__ __forceinline__ void cpwait0()  { asm volatile("cp.async.wait_group 0;" ::: "memory"); }

__device__ __forceinline__ uint32_t sw128(uint32_t o) { return o ^ ((o >> 3) & 0x70u); }

// ---------------- kernel A: style modulation + demodulated fp16 weights ----
__global__ void demod_kernel(const float* __restrict__ style,
                             const float* __restrict__ mw,
                             const float* __restrict__ mb,
                             const float* __restrict__ w) {
    int co = blockIdx.x;
    int b  = blockIdx.y;
    int tid = threadIdx.x;

    __shared__ float sdot[64];
    __shared__ float red[576];

    if (tid < 512) {
        int ci = tid >> 3;
        int j  = tid & 7;
        const float* sp = style + b * SDIM;
        const float* wp = mw + ci * SDIM;
        float sum = 0.f;
        #pragma unroll 8
        for (int t = 0; t < 64; t++)
            sum += sp[j + 8 * t] * wp[j + 8 * t];
        sum += __shfl_xor_sync(0xFFFFFFFFu, sum, 4);
        sum += __shfl_xor_sync(0xFFFFFFFFu, sum, 2);
        sum += __shfl_xor_sync(0xFFFFFFFFu, sum, 1);
        if (j == 0) sdot[ci] = sum * MOD_SCALE + mb[ci];
    }
    __syncthreads();

    int ci  = tid / TAPS;
    int tap = tid - ci * TAPS;
    float val = CONV_SCALE * w[(co * CIN + ci) * TAPS + tap] * sdot[ci];

    red[tid] = val * val;
    __syncthreads();
    if (tid < 64) red[tid] += red[tid + 512];
    __syncthreads();
    for (int s = 256; s > 0; s >>= 1) {
        if (tid < s) red[tid] += red[tid + s];
        __syncthreads();
    }
    float vd = val * rsqrtf(red[0] + EPSV);
    g_wt[(((size_t)b * TAPS + tap) * COUT + co) * CIN + ci] = __float2half_rn(vd);
}

// ---------------- kernel B: persistent conv, pipelined fragments -----------
// Work unit = chunk (xh, y4chunk, b): 128px x 64co x 4 rows (2 pairs).
// 8 warps (256 thr): 4 in M (32px) x 2 in N (32co), rows paired.
// Fragment double-buffering: LDSM for seg s+1 issues BEFORE mma of seg s,
// breaking the WAR chain that serialized crossbar and tensor pipe.
#define W_OFF      0u
#define W_BYTES    73728u
#define RING_OFF   73728u
#define ROW_STRIDE 16640u                        // 130 px x 128B
#define STAGE_OFF  (RING_OFF + 6u * ROW_STRIDE)  // 173568
#define STAGE_W    136                           // fp32 words per ci row
#define SMEM_TOTAL (STAGE_OFF + 64u * STAGE_W * 4u)   // 208384

#define NCTA       148

__global__ __launch_bounds__(256, 1)
void conv_kernel(const float* __restrict__ in, float* __restrict__ out) {
    extern __shared__ char smem[];
    const uint32_t sb = smem_u32(smem);
    const int tid  = threadIdx.x;
    const int wid  = tid >> 5;
    const int lane = tid & 31;

    const int mwarp = wid & 3;
    const int nwarp = wid >> 2;
    const uint32_t px0 = mwarp * 32;
    const uint32_t co0 = nwarp * 32;

    const uint32_t arow = lane & 15;
    const uint32_t khA  = ((lane >> 4) & 1) * 16;
    const uint32_t brow = (lane & 7) | ((lane >> 1) & 8);
    const uint32_t khB  = ((lane >> 3) & 1) * 16;

    // chunk range: 136 CTAs x 7, 12 CTAs x 6  (1024 = 136*7 + 12*6)
    const int cta = blockIdx.x;
    int c, cnt;
    if (cta < 136) { c = cta * 7;               cnt = 7; }
    else           { c = 952 + (cta - 136) * 6; cnt = 6; }

    float* sOut = (float*)(smem + STAGE_OFF);    // [64co][132px] f32 (reuses stage)
    const int eg = lane >> 2;
    const int et = lane & 3;

    int last_b = -1;

    while (cnt > 0) {
        const int col    = c >> 6;          // 16 columns = b(8) x xh(2)
        const int within = c & 63;
        const int b  = col >> 1;
        const int x0 = (col & 1) * 128;
        const int run = min(cnt, 64 - within);
        const int y0r = within * 4;
        const int npairs = run * 2;

        // ---- stage one raw fp32 input row into the stage buffer ----
        auto stage_async = [&](int iy) {
            if ((unsigned)iy >= 256u) return;
            #pragma unroll
            for (int it = 0; it < 9; it++) {
                int idx = tid + 256 * it;        // 64 ci x 34 chunks = 2176
                if (idx < 2176) {
                    int ci = idx / 34;
                    int cc = idx - ci * 34;
                    int gx0 = x0 - 4 + 4 * cc;
                    uint32_t doff = STAGE_OFF + (uint32_t)(ci * STAGE_W + 4 * cc) * 4u;
                    if ((unsigned)gx0 <= 252u) {
                        cpasync16(sb + doff,
                                  in + (((size_t)(b * CIN + ci)) * HH + iy) * WW + gx0);
                    } else {
                        *(uint4*)(smem + doff) = make_uint4(0, 0, 0, 0);
                    }
                }
            }
        };

        // ---- convert staged fp32 row -> swizzled fp16 ring slot ----
        auto convert_row = [&](int iy) {
            const uint32_t roff = RING_OFF
                + ((uint32_t)((iy + 1 + 768) % 6)) * ROW_STRIDE;
            const bool valid = ((unsigned)iy < 256u);
            const float* st = (const float*)(smem + STAGE_OFF);
            const int g = wid;
            #pragma unroll
            for (int it = 0; it < 5; it++) {
                int px = (it < 4) ? (it * 32 + lane) : (128 + lane);
                if (it == 4 && lane >= 2) break;
                float v[8];
                #pragma unroll
                for (int k = 0; k < 8; k++)
                    v[k] = valid ? st[(g * 8 + k) * STAGE_W + px + 3] : 0.f;
                uint32_t u[4];
                #pragma unroll
                for (int k = 0; k < 4; k++) {
                    __half2 hp = __floats2half2_rn(v[2 * k], v[2 * k + 1]);
                    u[k] = *reinterpret_cast<uint32_t*>(&hp);
                }
                *(uint4*)(smem + roff + sw128((uint32_t)px * 128u + (uint32_t)g * 16u))
                    = make_uint4(u[0], u[1], u[2], u[3]);
            }
        };

        // ---- run prologue: W (if b changed) + prime rows y0r-1..y0r+2 ----
        if (b != last_b) {
            const uint4* ws = ((const uint4*)g_wt) + (size_t)b * 4608;
            for (int j = tid; j < 4608; j += 256) {
                uint32_t o = (uint32_t)j << 4;
                cpasync16(sb + W_OFF + sw128(o), ws + j);
            }
            cpcommit();
            last_b = b;
        }
        #pragma unroll 1
        for (int rnd = 0; rnd < 4; rnd++) {
            stage_async(y0r - 1 + rnd);
            cpcommit();
            cpwait0();
            __syncthreads();
            convert_row(y0r - 1 + rnd);
            __syncthreads();
        }

        // ---- continuous pair loop across the whole run ----
        for (int q = 0; q < npairs; q++) {
            const int y = y0r + 2 * q;
            const bool more = (q < npairs - 1);

            if (more) { stage_async(y + 3); cpcommit(); }

            uint32_t rowA[4];
            #pragma unroll
            for (int j = 0; j < 4; j++)
                rowA[j] = sb + RING_OFF + ((uint32_t)((y + j) % 6)) * ROW_STRIDE;

            float acc[2][2][4][4];
            #pragma unroll
            for (int r = 0; r < 2; r++)
                #pragma unroll
                for (int mf = 0; mf < 2; mf++)
                    #pragma unroll
                    for (int nf = 0; nf < 4; nf++)
                        #pragma unroll
                        for (int cc = 0; cc < 4; cc++) acc[r][mf][nf][cc] = 0.f;

            // double-buffered fragments
            uint32_t afr[2][4][2][4];      // [buf][row][mf][4]
            uint32_t wfr[2][3][4][2];      // [buf][dy][nf][2]

            // prefetch fragments for segment s into buffer buf
            auto prefetch = [&](int s, int buf) {
                const int kc = s / 3;
                const uint32_t dx = (uint32_t)(s - 3 * kc);
                const uint32_t kb = (uint32_t)kc * 32u;
                #pragma unroll
                for (int dy = 0; dy < 3; dy++) {
                    const uint32_t tap = (uint32_t)(dy * 3) + dx;
                    #pragma unroll
                    for (int g = 0; g < 2; g++) {
                        uint32_t tmp[4];
                        uint32_t o = (tap * 64u + co0 + (uint32_t)g * 16u + brow) * 128u
                                     + kb + khB;
                        ldsm4(tmp, sb + W_OFF + sw128(o));
                        wfr[buf][dy][g * 2][0]     = tmp[0];
                        wfr[buf][dy][g * 2][1]     = tmp[1];
                        wfr[buf][dy][g * 2 + 1][0] = tmp[2];
                        wfr[buf][dy][g * 2 + 1][1] = tmp[3];
                    }
                }
                #pragma unroll
                for (int j = 0; j < 4; j++) {
                    #pragma unroll
                    for (int mf = 0; mf < 2; mf++) {
                        uint32_t o = (px0 + (uint32_t)mf * 16u + arow + dx) * 128u
                                     + kb + khA;
                        ldsm4(afr[buf][j][mf], rowA[j] + sw128(o));
                    }
                }
            };

            prefetch(0, 0);
            #pragma unroll
            for (int s = 0; s < 12; s++) {
                const int buf = s & 1;
                if (s < 11) prefetch(s + 1, buf ^ 1);
                #pragma unroll
                for (int dy = 0; dy < 3; dy++)
                    #pragma unroll
                    for (int r = 0; r < 2; r++)
                        #pragma unroll
                        for (int mf = 0; mf < 2; mf++)
                            #pragma unroll
                            for (int nf = 0; nf < 4; nf++)
                                mma16816(acc[r][mf][nf], afr[buf][r + dy][mf],
                                         wfr[buf][dy][nf][0], wfr[buf][dy][nf][1]);
                // mid-pair: consume staged row y+3, start staging row y+4
                if (s == 5 && more) {
                    cpwait0();
                    __syncthreads();
                    convert_row(y + 3);          // -> slot (y+4)%6 (free)
                    __syncthreads();
                    stage_async(y + 4);
                    cpcommit();
                }
            }

            if (more) {
                cpwait0();
                __syncthreads();
                convert_row(y + 4);              // -> slot (y+5)%6 (free)
            }
            __syncthreads();

            // ---- epilogue: two rows via smem transpose (stage reused) ----
            #pragma unroll
            for (int r = 0; r < 2; r++) {
                #pragma unroll
                for (int mf = 0; mf < 2; mf++) {
                    #pragma unroll
                    for (int nf = 0; nf < 4; nf++) {
                        int px = px0 + mf * 16 + eg;
                        int co = co0 + nf * 8 + 2 * et;
                        sOut[co * 132 + px]           = acc[r][mf][nf][0];
                        sOut[(co + 1) * 132 + px]     = acc[r][mf][nf][1];
                        sOut[co * 132 + px + 8]       = acc[r][mf][nf][2];
                        sOut[(co + 1) * 132 + px + 8] = acc[r][mf][nf][3];
                    }
                }
                __syncthreads();
                #pragma unroll
                for (int k = 0; k < 8; k++) {
                    int idx = tid + 256 * k;        // 2048 float4
                    int co = idx >> 5;
                    int qq = idx & 31;
                    float4 v = *(float4*)&sOut[co * 132 + qq * 4];
                    *(float4*)(out + (((size_t)b * COUT + co) * HH + (y + r)) * WW
                               + x0 + qq * 4) = v;
                }
                __syncthreads();
            }
        }

        c   += run;
        cnt -= run;
    }
}

// ---------------- launch ----------------
extern "C" void kernel_launch(void* const* d_in, const int* in_sizes, int n_in,
                              void* d_out, int out_size) {
    const float* input      = (const float*)d_in[0];
    const float* style      = (const float*)d_in[1];
    const float* weight     = (const float*)d_in[2];
    const float* mod_weight = (const float*)d_in[3];
    const float* mod_bias   = (const float*)d_in[4];
    float* out = (float*)d_out;

    cudaFuncSetAttribute(conv_kernel,
                         cudaFuncAttributeMaxDynamicSharedMemorySize, SMEM_TOTAL);

    demod_kernel<<<dim3(COUT, BATCH), 576>>>(style, mod_weight, mod_bias, weight);
    conv_kernel<<<NCTA, 256, SMEM_TOTAL>>>(input, out);
}